// round 12
// baseline (speedup 1.0000x reference)
#include <cuda_runtime.h>
#include <cuda_fp16.h>

#define NEG_SLOPE 0.2f
#define BN_EPS_F  1e-5f
#define FULLM 0xffffffffu

static constexpr int NMAX = 100000;
static constexpr int EMAX = 1700000;

// ---------------- scratch (static device globals; no allocation) ----------------
__device__ __half g_h1  [(size_t)NMAX * 128];   // fp16 activations (gather input only)
__device__ float  g_agg1[(size_t)NMAX * 128];   // fp32 (BN + GEMM2 input)
__device__ __half g_h2  [(size_t)NMAX * 80];
__device__ float2 g_as1 [NMAX];
__device__ float2 g_ad1 [NMAX];
__device__ float2 g_as2 [NMAX];
__device__ float2 g_ad2 [NMAX];
__device__ int    g_deg   [NMAX];
__device__ int    g_incl  [NMAX];
__device__ int    g_rowptr[NMAX + 1];
__device__ int    g_cursor[NMAX];
__device__ int    g_col   [EMAX];
__device__ int    g_bsum  [256];
__device__ float  g_colsum[128];
__device__ float  g_colsq [128];
__device__ float  g_scale [128];
__device__ float  g_shift [128];

// ---------------- packed f32x2 helpers (sm_103a FFMA2 path) ----------------
__device__ __forceinline__ unsigned long long pack2(float lo, float hi) {
    unsigned long long r;
    asm("mov.b64 %0, {%1, %2};" : "=l"(r) : "f"(lo), "f"(hi));
    return r;
}
__device__ __forceinline__ void fma2(unsigned long long& d, unsigned long long a,
                                     unsigned long long b) {
    asm("fma.rn.f32x2 %0, %1, %2, %0;" : "+l"(d) : "l"(a), "l"(b));
}
__device__ __forceinline__ void unpack2(unsigned long long v, float& lo, float& hi) {
    asm("mov.b64 {%0, %1}, %2;" : "=f"(lo), "=f"(hi) : "l"(v));
}

// ---------------- CSR build ----------------
__global__ void hist_k(const int* __restrict__ dst, int* __restrict__ deg, int E) {
    int e = blockIdx.x * blockDim.x + threadIdx.x;
    if (e < E) atomicAdd(&deg[dst[e]], 1);
}

// per-block (1024) inclusive scan + block sums
__global__ void scan1_k(const int* __restrict__ deg, int* __restrict__ incl,
                        int* __restrict__ bsum, int n) {
    __shared__ int wsum[32];
    const int tid = threadIdx.x;
    const int gid = blockIdx.x * 1024 + tid;
    const int lane = tid & 31, w = tid >> 5;
    int x = (gid < n) ? deg[gid] : 0;
    #pragma unroll
    for (int o = 1; o < 32; o <<= 1) {
        int t = __shfl_up_sync(FULLM, x, o);
        if (lane >= o) x += t;
    }
    if (lane == 31) wsum[w] = x;
    __syncthreads();
    if (w == 0) {
        int y = wsum[lane];
        #pragma unroll
        for (int o = 1; o < 32; o <<= 1) {
            int t = __shfl_up_sync(FULLM, y, o);
            if (lane >= o) y += t;
        }
        wsum[lane] = y;
    }
    __syncthreads();
    if (w > 0) x += wsum[w - 1];
    if (gid < n) incl[gid] = x;
    if (tid == 1023) bsum[blockIdx.x] = x;
}

// rowptr + cursor; each block redundantly exclusive-scans bsum (<=128 vals) in smem
__global__ void scan3_k(const int* __restrict__ incl, const int* __restrict__ bsum,
                        const int* __restrict__ deg, int* __restrict__ rowptr,
                        int* __restrict__ cursor, int n, int nb) {
    __shared__ int pre[128];
    __shared__ int ws[4];
    const int tid = threadIdx.x;
    if (tid < 128) {
        const int lane = tid & 31, w = tid >> 5;
        int orig = (tid < nb) ? bsum[tid] : 0;
        int x = orig;
        #pragma unroll
        for (int o = 1; o < 32; o <<= 1) {
            int t = __shfl_up_sync(FULLM, x, o);
            if (lane >= o) x += t;
        }
        if (lane == 31) ws[w] = x;
        __syncwarp();
        pre[tid] = x - orig;   // exclusive within warp
    }
    __syncthreads();
    if (tid < 128) {
        const int w = tid >> 5;
        int add = 0;
        #pragma unroll
        for (int k = 0; k < 4; k++) if (k < w) add += ws[k];
        pre[tid] += add;       // exclusive across all 128
    }
    __syncthreads();

    int i = blockIdx.x * blockDim.x + tid;
    if (i < n) {
        int v = incl[i] + pre[i >> 10];
        rowptr[i + 1] = v;
        cursor[i] = v - deg[i];
    }
    if (i == 0) rowptr[0] = 0;
}

__global__ void fill_k(const int* __restrict__ src, const int* __restrict__ dst,
                       int* __restrict__ cursor, int* __restrict__ col, int E) {
    int e = blockIdx.x * blockDim.x + threadIdx.x;
    if (e < E) {
        int p = atomicAdd(&cursor[dst[e]], 1);
        col[p] = src[e];
    }
}

// ---- GEMM: H[n,NOUT](fp16) = X[n,128] @ W[128,NOUT] via packed f32x2 FMA.
//      Optional BN fold on X load; fused AS/AD attention epilogue (fp32 exact). ----
template<int NOUT>
__global__ __launch_bounds__(256, 2)
void gemm_k(const float* __restrict__ X, const float* __restrict__ W,
            __half* __restrict__ H, int n,
            const float* __restrict__ scale, const float* __restrict__ shift,
            const float* __restrict__ attS, const float* __restrict__ attD,
            float2* __restrict__ AS, float2* __restrict__ AD)
{
    constexpr int TN = (NOUT == 128) ? 8 : 5;
    constexpr int NP = TN / 2;
    constexpr bool ODD = (TN & 1) != 0;
    constexpr int HALF = NOUT / 2;

    extern __shared__ float smem[];
    float* sW = smem;                           // [128 * NOUT]
    float* sX = smem + 128 * NOUT;              // [64 * 132]

    const int tid = threadIdx.x;
    const int tx  = tid & 15;
    const int ty  = tid >> 4;
    const int row0 = blockIdx.x * 64;

    for (int i = tid; i < 128 * NOUT; i += 256) sW[i] = W[i];
    const bool bn = (scale != nullptr);
    for (int i = tid; i < 64 * 128; i += 256) {
        int r = i >> 7, c = i & 127;
        int gr = row0 + r;
        float v = (gr < n) ? X[(size_t)gr * 128 + c] : 0.0f;
        if (bn) v = fmaf(v, scale[c], shift[c]);
        sX[r * 132 + c] = v;
    }
    __syncthreads();

    unsigned long long acc2[4][NP];
    float acco[4];
    #pragma unroll
    for (int i = 0; i < 4; i++) {
        #pragma unroll
        for (int p = 0; p < NP; p++) acc2[i][p] = 0ull;
        acco[i] = 0.f;
    }

    #pragma unroll 8
    for (int k = 0; k < 128; k++) {
        float a[4];
        unsigned long long a2[4];
        #pragma unroll
        for (int i = 0; i < 4; i++) {
            a[i] = sX[(ty * 4 + i) * 132 + k];
            a2[i] = pack2(a[i], a[i]);
        }
        unsigned long long bp[NP];
        float bo = 0.f;
        if constexpr (NOUT == 128) {
            const float4* q = reinterpret_cast<const float4*>(sW + k * 128 + tx * 8);
            float4 b0 = q[0], b1 = q[1];
            bp[0] = pack2(b0.x, b0.y); bp[1] = pack2(b0.z, b0.w);
            bp[2] = pack2(b1.x, b1.y); bp[3] = pack2(b1.z, b1.w);
        } else {
            float4 b0 = *reinterpret_cast<const float4*>(sW + k * 80 + tx * 4);
            bp[0] = pack2(b0.x, b0.y); bp[1] = pack2(b0.z, b0.w);
            bo = sW[k * 80 + 64 + tx];
        }
        #pragma unroll
        for (int i = 0; i < 4; i++) {
            #pragma unroll
            for (int p = 0; p < NP; p++) fma2(acc2[i][p], a2[i], bp[p]);
            if constexpr (ODD) acco[i] = fmaf(a[i], bo, acco[i]);
        }
    }

    float acc[4][TN];
    #pragma unroll
    for (int i = 0; i < 4; i++) {
        #pragma unroll
        for (int p = 0; p < NP; p++) unpack2(acc2[i][p], acc[i][2 * p], acc[i][2 * p + 1]);
        if constexpr (ODD) acc[i][TN - 1] = acco[i];
    }

    int cmap[TN];
    #pragma unroll
    for (int j = 0; j < TN; j++) {
        if constexpr (NOUT == 128) cmap[j] = tx * 8 + j;
        else cmap[j] = (j < 4) ? (tx * 4 + j) : (64 + tx);
    }

    // store H as fp16 (vectorized)
    #pragma unroll
    for (int i = 0; i < 4; i++) {
        int gr = row0 + ty * 4 + i;
        if (gr < n) {
            if constexpr (NOUT == 128) {
                __half2 h0 = __floats2half2_rn(acc[i][0], acc[i][1]);
                __half2 h1v = __floats2half2_rn(acc[i][2], acc[i][3]);
                __half2 h2v = __floats2half2_rn(acc[i][4], acc[i][5]);
                __half2 h3 = __floats2half2_rn(acc[i][6], acc[i][7]);
                uint4 pkt;
                pkt.x = *reinterpret_cast<unsigned int*>(&h0);
                pkt.y = *reinterpret_cast<unsigned int*>(&h1v);
                pkt.z = *reinterpret_cast<unsigned int*>(&h2v);
                pkt.w = *reinterpret_cast<unsigned int*>(&h3);
                *reinterpret_cast<uint4*>(H + (size_t)gr * 128 + tx * 8) = pkt;
            } else {
                __half2 h0 = __floats2half2_rn(acc[i][0], acc[i][1]);
                __half2 h1v = __floats2half2_rn(acc[i][2], acc[i][3]);
                uint2 pkt;
                pkt.x = *reinterpret_cast<unsigned int*>(&h0);
                pkt.y = *reinterpret_cast<unsigned int*>(&h1v);
                *reinterpret_cast<uint2*>(H + (size_t)gr * 80 + tx * 4) = pkt;
                H[(size_t)gr * 80 + 64 + tx] = __float2half_rn(acc[i][4]);
            }
        }
    }

    // fused attention dot products (fp32 exact), per head, 16-lane reduce
    float av[TN], dv[TN];
    #pragma unroll
    for (int j = 0; j < TN; j++) {
        av[j] = attS[cmap[j]];
        dv[j] = attD[cmap[j]];
    }
    #pragma unroll
    for (int i = 0; i < 4; i++) {
        float ps0 = 0.f, ps1 = 0.f, pd0 = 0.f, pd1 = 0.f;
        #pragma unroll
        for (int j = 0; j < TN; j++) {
            if (cmap[j] < HALF) {
                ps0 = fmaf(acc[i][j], av[j], ps0);
                pd0 = fmaf(acc[i][j], dv[j], pd0);
            } else {
                ps1 = fmaf(acc[i][j], av[j], ps1);
                pd1 = fmaf(acc[i][j], dv[j], pd1);
            }
        }
        #pragma unroll
        for (int o = 1; o < 16; o <<= 1) {
            ps0 += __shfl_xor_sync(FULLM, ps0, o);
            ps1 += __shfl_xor_sync(FULLM, ps1, o);
            pd0 += __shfl_xor_sync(FULLM, pd0, o);
            pd1 += __shfl_xor_sync(FULLM, pd1, o);
        }
        int gr = row0 + ty * 4 + i;
        if (tx == 0 && gr < n) {
            AS[gr] = make_float2(ps0, ps1);
            AD[gr] = make_float2(pd0, pd1);
        }
    }
}

// ---- layer-1 gather: warp per dst node; fp16 rows, fp32 accumulate, unroll 4 ----
__global__ __launch_bounds__(256)
void gather1_k(const int* __restrict__ rowptr, const int* __restrict__ col,
               const float2* __restrict__ AS, const float2* __restrict__ AD,
               const __half* __restrict__ H, const float* __restrict__ b1,
               float* __restrict__ OUT, int n)
{
    const int lane = threadIdx.x & 31;
    const int i = (blockIdx.x * blockDim.x + threadIdx.x) >> 5;
    if (i >= n) return;
    const bool hs = lane >= 16;               // head1 for cols >= 64
    const float2 adv = AD[i];
    const float ad = hs ? adv.y : adv.x;

    float4 acc = make_float4(0.f, 0.f, 0.f, 0.f);
    float den = 0.f;
    const int beg = rowptr[i], end = rowptr[i + 1];
    #pragma unroll 4
    for (int e = beg; e < end; e++) {
        const int s = __ldg(col + e);
        const float2 asv = __ldg(AS + s);
        float a = (hs ? asv.y : asv.x) + ad;
        a = a > 0.f ? a : NEG_SLOPE * a;
        const float w = __expf(a);
        den += w;
        const uint2 raw = *reinterpret_cast<const uint2*>(H + (size_t)s * 128 + lane * 4);
        const float2 f01 = __half22float2(*reinterpret_cast<const __half2*>(&raw.x));
        const float2 f23 = __half22float2(*reinterpret_cast<const __half2*>(&raw.y));
        acc.x = fmaf(w, f01.x, acc.x); acc.y = fmaf(w, f01.y, acc.y);
        acc.z = fmaf(w, f23.x, acc.z); acc.w = fmaf(w, f23.y, acc.w);
    }
    // self loop
    {
        const float2 asv = AS[i];
        float a = (hs ? asv.y : asv.x) + ad;
        a = a > 0.f ? a : NEG_SLOPE * a;
        const float w = __expf(a);
        den += w;
        const uint2 raw = *reinterpret_cast<const uint2*>(H + (size_t)i * 128 + lane * 4);
        const float2 f01 = __half22float2(*reinterpret_cast<const __half2*>(&raw.x));
        const float2 f23 = __half22float2(*reinterpret_cast<const __half2*>(&raw.y));
        acc.x = fmaf(w, f01.x, acc.x); acc.y = fmaf(w, f01.y, acc.y);
        acc.z = fmaf(w, f23.x, acc.z); acc.w = fmaf(w, f23.y, acc.w);
    }
    const float inv = 1.0f / den;
    const float4 bv = *reinterpret_cast<const float4*>(b1 + lane * 4);
    float4 o;
    o.x = acc.x * inv + bv.x; o.y = acc.y * inv + bv.y;
    o.z = acc.z * inv + bv.z; o.w = acc.w * inv + bv.w;
    *reinterpret_cast<float4*>(OUT + (size_t)i * 128 + lane * 4) = o;
}

// ---- per-column sum / sumsq over agg1 ----
__global__ void bnstats_k(const float* __restrict__ A, float* __restrict__ colsum,
                          float* __restrict__ colsq, int n)
{
    const int c = threadIdx.x;                 // 128 threads
    const int r0 = blockIdx.x * 256;
    const int r1 = min(r0 + 256, n);
    float s = 0.f, q = 0.f;
    for (int r = r0; r < r1; r++) {
        float v = A[(size_t)r * 128 + c];
        s += v; q = fmaf(v, v, q);
    }
    atomicAdd(&colsum[c], s);
    atomicAdd(&colsq[c], q);
}

__global__ void bnfold_k(const float* __restrict__ colsum, const float* __restrict__ colsq,
                         const float* __restrict__ gamma, const float* __restrict__ beta,
                         float* __restrict__ scale, float* __restrict__ shift, int n)
{
    const int t = threadIdx.x;
    float inv_n = 1.0f / (float)n;
    float mean = colsum[t] * inv_n;
    float var  = colsq[t] * inv_n - mean * mean;
    float sc   = gamma[t] * rsqrtf(var + BN_EPS_F);
    scale[t] = sc;
    shift[t] = beta[t] - mean * sc;
}

// ---- layer-2 gather (fp16 rows, unroll 4) + head-mean + bias + log_softmax ----
__global__ __launch_bounds__(256)
void gather2_k(const int* __restrict__ rowptr, const int* __restrict__ col,
               const float2* __restrict__ AS, const float2* __restrict__ AD,
               const __half* __restrict__ H, const float* __restrict__ b2,
               float* __restrict__ out, int n)
{
    const int lane = threadIdx.x & 31;
    const int i = (blockIdx.x * blockDim.x + threadIdx.x) >> 5;
    if (i >= n) return;
    const bool act = lane < 20;               // lane*4 < 80
    const bool hs  = lane >= 10;              // head1 for cols >= 40
    const float2 adv = AD[i];
    const float ad = hs ? adv.y : adv.x;

    float4 acc = make_float4(0.f, 0.f, 0.f, 0.f);
    float den = 0.f;
    const int beg = rowptr[i], end = rowptr[i + 1];
    #pragma unroll 4
    for (int e = beg; e < end; e++) {
        const int s = __ldg(col + e);
        const float2 asv = __ldg(AS + s);
        float a = (hs ? asv.y : asv.x) + ad;
        a = a > 0.f ? a : NEG_SLOPE * a;
        const float w = __expf(a);
        den += w;
        if (act) {
            const uint2 raw = *reinterpret_cast<const uint2*>(H + (size_t)s * 80 + lane * 4);
            const float2 f01 = __half22float2(*reinterpret_cast<const __half2*>(&raw.x));
            const float2 f23 = __half22float2(*reinterpret_cast<const __half2*>(&raw.y));
            acc.x = fmaf(w, f01.x, acc.x); acc.y = fmaf(w, f01.y, acc.y);
            acc.z = fmaf(w, f23.x, acc.z); acc.w = fmaf(w, f23.y, acc.w);
        }
    }
    // self loop
    {
        const float2 asv = AS[i];
        float a = (hs ? asv.y : asv.x) + ad;
        a = a > 0.f ? a : NEG_SLOPE * a;
        const float w = __expf(a);
        den += w;
        if (act) {
            const uint2 raw = *reinterpret_cast<const uint2*>(H + (size_t)i * 80 + lane * 4);
            const float2 f01 = __half22float2(*reinterpret_cast<const __half2*>(&raw.x));
            const float2 f23 = __half22float2(*reinterpret_cast<const __half2*>(&raw.y));
            acc.x = fmaf(w, f01.x, acc.x); acc.y = fmaf(w, f01.y, acc.y);
            acc.z = fmaf(w, f23.x, acc.z); acc.w = fmaf(w, f23.y, acc.w);
        }
    }
    const float inv = 1.0f / den;
    float4 v;
    v.x = acc.x * inv; v.y = acc.y * inv; v.z = acc.z * inv; v.w = acc.w * inv;

    // head mean: lanes 0..9 pair with lanes 10..19
    float4 o;
    o.x = __shfl_sync(FULLM, v.x, lane + 10);
    o.y = __shfl_sync(FULLM, v.y, lane + 10);
    o.z = __shfl_sync(FULLM, v.z, lane + 10);
    o.w = __shfl_sync(FULLM, v.w, lane + 10);

    float4 m = make_float4(-1e30f, -1e30f, -1e30f, -1e30f);
    if (lane < 10) {
        const float4 bv = *reinterpret_cast<const float4*>(b2 + lane * 4);
        m.x = 0.5f * (v.x + o.x) + bv.x;
        m.y = 0.5f * (v.y + o.y) + bv.y;
        m.z = 0.5f * (v.z + o.z) + bv.z;
        m.w = 0.5f * (v.w + o.w) + bv.w;
    }
    float mm = fmaxf(fmaxf(m.x, m.y), fmaxf(m.z, m.w));
    #pragma unroll
    for (int off = 16; off > 0; off >>= 1)
        mm = fmaxf(mm, __shfl_xor_sync(FULLM, mm, off));
    float ssum = 0.f;
    if (lane < 10)
        ssum = __expf(m.x - mm) + __expf(m.y - mm) + __expf(m.z - mm) + __expf(m.w - mm);
    #pragma unroll
    for (int off = 16; off > 0; off >>= 1)
        ssum += __shfl_xor_sync(FULLM, ssum, off);
    const float lse = mm + __logf(ssum);

    if (lane < 10) {
        float4 r;
        r.x = m.x - lse; r.y = m.y - lse; r.z = m.z - lse; r.w = m.w - lse;
        *reinterpret_cast<float4*>(out + (size_t)i * 40 + lane * 4) = r;
    }
}

// ------------------------------- launcher -------------------------------
extern "C" void kernel_launch(void* const* d_in, const int* in_sizes, int n_in,
                              void* d_out, int out_size)
{
    const float* x      = (const float*)d_in[0];
    const int*   ei     = (const int*)  d_in[1];
    const float* W1     = (const float*)d_in[2];
    const float* att_s1 = (const float*)d_in[3];
    const float* att_d1 = (const float*)d_in[4];
    const float* b1     = (const float*)d_in[5];
    const float* gamma  = (const float*)d_in[6];
    const float* beta   = (const float*)d_in[7];
    const float* W2     = (const float*)d_in[8];
    const float* att_s2 = (const float*)d_in[9];
    const float* att_d2 = (const float*)d_in[10];
    const float* b2     = (const float*)d_in[11];
    float* out = (float*)d_out;

    const int n = in_sizes[0] / 128;
    const int E = in_sizes[1] / 2;
    const int* src = ei;
    const int* dst = ei + E;

    float *agg1, *colsum, *colsq, *scale, *shift;
    __half *h1, *h2;
    float2 *as1, *ad1, *as2, *ad2;
    int *deg, *incl, *rowptr, *cursor, *colarr, *bsum;
    cudaGetSymbolAddress((void**)&h1,     g_h1);
    cudaGetSymbolAddress((void**)&agg1,   g_agg1);
    cudaGetSymbolAddress((void**)&h2,     g_h2);
    cudaGetSymbolAddress((void**)&as1,    g_as1);
    cudaGetSymbolAddress((void**)&ad1,    g_ad1);
    cudaGetSymbolAddress((void**)&as2,    g_as2);
    cudaGetSymbolAddress((void**)&ad2,    g_ad2);
    cudaGetSymbolAddress((void**)&deg,    g_deg);
    cudaGetSymbolAddress((void**)&incl,   g_incl);
    cudaGetSymbolAddress((void**)&rowptr, g_rowptr);
    cudaGetSymbolAddress((void**)&cursor, g_cursor);
    cudaGetSymbolAddress((void**)&colarr, g_col);
    cudaGetSymbolAddress((void**)&bsum,   g_bsum);
    cudaGetSymbolAddress((void**)&colsum, g_colsum);
    cudaGetSymbolAddress((void**)&colsq,  g_colsq);
    cudaGetSymbolAddress((void**)&scale,  g_scale);
    cudaGetSymbolAddress((void**)&shift,  g_shift);

    const size_t smem1 = (128 * 128 + 64 * 132) * sizeof(float);  // 99328 B
    const size_t smem2 = (128 * 80  + 64 * 132) * sizeof(float);  // 74752 B
    cudaFuncSetAttribute((const void*)gemm_k<128>, cudaFuncAttributeMaxDynamicSharedMemorySize, (int)smem1);
    cudaFuncSetAttribute((const void*)gemm_k<80>,  cudaFuncAttributeMaxDynamicSharedMemorySize, (int)smem2);

    const int gb = (n + 63) / 64;         // gemm blocks
    const int wb = (n * 32 + 255) / 256;  // warp-per-node blocks
    const int nb = (n + 1023) / 1024;     // scan blocks

    // ---- CSR build (zeroing via memset nodes — not kernel launches) ----
    cudaMemsetAsync(deg, 0, n * sizeof(int));
    cudaMemsetAsync(colsum, 0, 128 * sizeof(float));
    cudaMemsetAsync(colsq, 0, 128 * sizeof(float));
    hist_k<<<(E + 255) / 256, 256>>>(dst, deg, E);                   // launch 1
    scan1_k<<<nb, 1024>>>(deg, incl, bsum, n);                       // 2
    scan3_k<<<(n + 255) / 256, 256>>>(incl, bsum, deg, rowptr, cursor, n, nb); // 3
    fill_k<<<(E + 255) / 256, 256>>>(src, dst, cursor, colarr, E);   // 4

    // ---- layer 1 ----
    gemm_k<128><<<gb, 256, smem1>>>(x, W1, h1, n, nullptr, nullptr,  // 5
                                    att_s1, att_d1, as1, ad1);
    gather1_k<<<wb, 256>>>(rowptr, colarr, as1, ad1, h1, b1, agg1, n); // 6 <- ncu -s 5

    // ---- batchnorm stats + fold ----
    bnstats_k<<<(n + 255) / 256, 128>>>(agg1, colsum, colsq, n);
    bnfold_k<<<1, 128>>>(colsum, colsq, gamma, beta, scale, shift, n);

    // ---- layer 2 (BN folded into GEMM A-load) ----
    gemm_k<80><<<gb, 256, smem2>>>(agg1, W2, h2, n, scale, shift,
                                   att_s2, att_d2, as2, ad2);
    gather2_k<<<wb, 256>>>(rowptr, colarr, as2, ad2, h2, b2, out, n);
}

// round 13
// speedup vs baseline: 1.4888x; 1.4888x over previous
#include <cuda_runtime.h>
#include <cuda_fp16.h>

#define NEG_SLOPE 0.2f
#define BN_EPS_F  1e-5f
#define FULLM 0xffffffffu

static constexpr int NMAX = 100000;
static constexpr int EMAX = 1700000;

// ---------------- scratch (static device globals; no allocation) ----------------
__device__ __half g_h1  [(size_t)NMAX * 128];   // fp16 activations (gather input only)
__device__ float  g_agg1[(size_t)NMAX * 128];   // fp32 (BN + GEMM2 input)
__device__ __half g_h2  [(size_t)NMAX * 80];
__device__ float2 g_as1 [NMAX];
__device__ float2 g_ad1 [NMAX];
__device__ float2 g_as2 [NMAX];
__device__ float2 g_ad2 [NMAX];
__device__ int    g_deg   [NMAX];
__device__ int    g_incl  [NMAX];
__device__ int    g_rowptr[NMAX + 1];
__device__ int    g_cursor[NMAX];
__device__ int    g_col   [EMAX];
__device__ int    g_bsum  [256];
__device__ float  g_colsum[128];
__device__ float  g_colsq [128];
__device__ float  g_scale [128];
__device__ float  g_shift [128];

// ---------------- packed f32x2 helpers (sm_103a FFMA2 path) ----------------
__device__ __forceinline__ unsigned long long pack2(float lo, float hi) {
    unsigned long long r;
    asm("mov.b64 %0, {%1, %2};" : "=l"(r) : "f"(lo), "f"(hi));
    return r;
}
__device__ __forceinline__ void fma2(unsigned long long& d, unsigned long long a,
                                     unsigned long long b) {
    asm("fma.rn.f32x2 %0, %1, %2, %0;" : "+l"(d) : "l"(a), "l"(b));
}
__device__ __forceinline__ void unpack2(unsigned long long v, float& lo, float& hi) {
    asm("mov.b64 {%0, %1}, %2;" : "=f"(lo), "=f"(hi) : "l"(v));
}

// ---------------- CSR build ----------------
__global__ void zero_init_k(int* deg, float* colsum, float* colsq, int n) {
    int i = blockIdx.x * blockDim.x + threadIdx.x;
    if (i < n) deg[i] = 0;
    if (i < 128) { colsum[i] = 0.f; colsq[i] = 0.f; }
}

__global__ void hist_k(const int* __restrict__ dst, int* __restrict__ deg, int E) {
    int e = blockIdx.x * blockDim.x + threadIdx.x;
    if (e < E) atomicAdd(&deg[dst[e]], 1);
}

// per-block (1024) inclusive scan + block sums
__global__ void scan1_k(const int* __restrict__ deg, int* __restrict__ incl,
                        int* __restrict__ bsum, int n) {
    __shared__ int wsum[32];
    const int tid = threadIdx.x;
    const int gid = blockIdx.x * 1024 + tid;
    const int lane = tid & 31, w = tid >> 5;
    int x = (gid < n) ? deg[gid] : 0;
    #pragma unroll
    for (int o = 1; o < 32; o <<= 1) {
        int t = __shfl_up_sync(FULLM, x, o);
        if (lane >= o) x += t;
    }
    if (lane == 31) wsum[w] = x;
    __syncthreads();
    if (w == 0) {
        int y = wsum[lane];
        #pragma unroll
        for (int o = 1; o < 32; o <<= 1) {
            int t = __shfl_up_sync(FULLM, y, o);
            if (lane >= o) y += t;
        }
        wsum[lane] = y;
    }
    __syncthreads();
    if (w > 0) x += wsum[w - 1];
    if (gid < n) incl[gid] = x;
    if (tid == 1023) bsum[blockIdx.x] = x;
}

// rowptr + cursor; each block redundantly exclusive-scans bsum (<=128 vals) in smem
__global__ void scan3_k(const int* __restrict__ incl, const int* __restrict__ bsum,
                        const int* __restrict__ deg, int* __restrict__ rowptr,
                        int* __restrict__ cursor, int n, int nb) {
    __shared__ int pre[128];
    __shared__ int ws[4];
    const int tid = threadIdx.x;
    if (tid < 128) {
        const int lane = tid & 31, w = tid >> 5;
        int orig = (tid < nb) ? bsum[tid] : 0;
        int x = orig;
        #pragma unroll
        for (int o = 1; o < 32; o <<= 1) {
            int t = __shfl_up_sync(FULLM, x, o);
            if (lane >= o) x += t;
        }
        if (lane == 31) ws[w] = x;
        __syncwarp();
        pre[tid] = x - orig;   // exclusive within warp
    }
    __syncthreads();
    if (tid < 128) {
        const int w = tid >> 5;
        int add = 0;
        #pragma unroll
        for (int k = 0; k < 4; k++) if (k < w) add += ws[k];
        pre[tid] += add;       // exclusive across all 128
    }
    __syncthreads();

    int i = blockIdx.x * blockDim.x + tid;
    if (i < n) {
        int v = incl[i] + pre[i >> 10];
        rowptr[i + 1] = v;
        cursor[i] = v - deg[i];
    }
    if (i == 0) rowptr[0] = 0;
}

__global__ void fill_k(const int* __restrict__ src, const int* __restrict__ dst,
                       int* __restrict__ cursor, int* __restrict__ col, int E) {
    int e = blockIdx.x * blockDim.x + threadIdx.x;
    if (e < E) {
        int p = atomicAdd(&cursor[dst[e]], 1);
        col[p] = src[e];
    }
}

// ---- GEMM: H[n,NOUT](fp16) = X[n,128] @ W[128,NOUT] via packed f32x2 FMA.
//      Optional BN fold on X load; fused AS/AD attention epilogue (fp32 exact). ----
template<int NOUT>
__global__ __launch_bounds__(256, 2)
void gemm_k(const float* __restrict__ X, const float* __restrict__ W,
            __half* __restrict__ H, int n,
            const float* __restrict__ scale, const float* __restrict__ shift,
            const float* __restrict__ attS, const float* __restrict__ attD,
            float2* __restrict__ AS, float2* __restrict__ AD)
{
    constexpr int TN = (NOUT == 128) ? 8 : 5;
    constexpr int NP = TN / 2;
    constexpr bool ODD = (TN & 1) != 0;
    constexpr int HALF = NOUT / 2;

    extern __shared__ float smem[];
    float* sW = smem;                           // [128 * NOUT]
    float* sX = smem + 128 * NOUT;              // [64 * 132]

    const int tid = threadIdx.x;
    const int tx  = tid & 15;
    const int ty  = tid >> 4;
    const int row0 = blockIdx.x * 64;

    for (int i = tid; i < 128 * NOUT; i += 256) sW[i] = W[i];
    const bool bn = (scale != nullptr);
    for (int i = tid; i < 64 * 128; i += 256) {
        int r = i >> 7, c = i & 127;
        int gr = row0 + r;
        float v = (gr < n) ? X[(size_t)gr * 128 + c] : 0.0f;
        if (bn) v = fmaf(v, scale[c], shift[c]);
        sX[r * 132 + c] = v;
    }
    __syncthreads();

    unsigned long long acc2[4][NP];
    float acco[4];
    #pragma unroll
    for (int i = 0; i < 4; i++) {
        #pragma unroll
        for (int p = 0; p < NP; p++) acc2[i][p] = 0ull;
        acco[i] = 0.f;
    }

    #pragma unroll 8
    for (int k = 0; k < 128; k++) {
        float a[4];
        unsigned long long a2[4];
        #pragma unroll
        for (int i = 0; i < 4; i++) {
            a[i] = sX[(ty * 4 + i) * 132 + k];
            a2[i] = pack2(a[i], a[i]);
        }
        unsigned long long bp[NP];
        float bo = 0.f;
        if constexpr (NOUT == 128) {
            const float4* q = reinterpret_cast<const float4*>(sW + k * 128 + tx * 8);
            float4 b0 = q[0], b1 = q[1];
            bp[0] = pack2(b0.x, b0.y); bp[1] = pack2(b0.z, b0.w);
            bp[2] = pack2(b1.x, b1.y); bp[3] = pack2(b1.z, b1.w);
        } else {
            float4 b0 = *reinterpret_cast<const float4*>(sW + k * 80 + tx * 4);
            bp[0] = pack2(b0.x, b0.y); bp[1] = pack2(b0.z, b0.w);
            bo = sW[k * 80 + 64 + tx];
        }
        #pragma unroll
        for (int i = 0; i < 4; i++) {
            #pragma unroll
            for (int p = 0; p < NP; p++) fma2(acc2[i][p], a2[i], bp[p]);
            if constexpr (ODD) acco[i] = fmaf(a[i], bo, acco[i]);
        }
    }

    float acc[4][TN];
    #pragma unroll
    for (int i = 0; i < 4; i++) {
        #pragma unroll
        for (int p = 0; p < NP; p++) unpack2(acc2[i][p], acc[i][2 * p], acc[i][2 * p + 1]);
        if constexpr (ODD) acc[i][TN - 1] = acco[i];
    }

    int cmap[TN];
    #pragma unroll
    for (int j = 0; j < TN; j++) {
        if constexpr (NOUT == 128) cmap[j] = tx * 8 + j;
        else cmap[j] = (j < 4) ? (tx * 4 + j) : (64 + tx);
    }

    // store H as fp16 (vectorized)
    #pragma unroll
    for (int i = 0; i < 4; i++) {
        int gr = row0 + ty * 4 + i;
        if (gr < n) {
            if constexpr (NOUT == 128) {
                __half2 h0 = __floats2half2_rn(acc[i][0], acc[i][1]);
                __half2 h1v = __floats2half2_rn(acc[i][2], acc[i][3]);
                __half2 h2v = __floats2half2_rn(acc[i][4], acc[i][5]);
                __half2 h3 = __floats2half2_rn(acc[i][6], acc[i][7]);
                uint4 pkt;
                pkt.x = *reinterpret_cast<unsigned int*>(&h0);
                pkt.y = *reinterpret_cast<unsigned int*>(&h1v);
                pkt.z = *reinterpret_cast<unsigned int*>(&h2v);
                pkt.w = *reinterpret_cast<unsigned int*>(&h3);
                *reinterpret_cast<uint4*>(H + (size_t)gr * 128 + tx * 8) = pkt;
            } else {
                __half2 h0 = __floats2half2_rn(acc[i][0], acc[i][1]);
                __half2 h1v = __floats2half2_rn(acc[i][2], acc[i][3]);
                uint2 pkt;
                pkt.x = *reinterpret_cast<unsigned int*>(&h0);
                pkt.y = *reinterpret_cast<unsigned int*>(&h1v);
                *reinterpret_cast<uint2*>(H + (size_t)gr * 80 + tx * 4) = pkt;
                H[(size_t)gr * 80 + 64 + tx] = __float2half_rn(acc[i][4]);
            }
        }
    }

    // fused attention dot products (fp32 exact), per head, 16-lane reduce
    float av[TN], dv[TN];
    #pragma unroll
    for (int j = 0; j < TN; j++) {
        av[j] = attS[cmap[j]];
        dv[j] = attD[cmap[j]];
    }
    #pragma unroll
    for (int i = 0; i < 4; i++) {
        float ps0 = 0.f, ps1 = 0.f, pd0 = 0.f, pd1 = 0.f;
        #pragma unroll
        for (int j = 0; j < TN; j++) {
            if (cmap[j] < HALF) {
                ps0 = fmaf(acc[i][j], av[j], ps0);
                pd0 = fmaf(acc[i][j], dv[j], pd0);
            } else {
                ps1 = fmaf(acc[i][j], av[j], ps1);
                pd1 = fmaf(acc[i][j], dv[j], pd1);
            }
        }
        #pragma unroll
        for (int o = 1; o < 16; o <<= 1) {
            ps0 += __shfl_xor_sync(FULLM, ps0, o);
            ps1 += __shfl_xor_sync(FULLM, ps1, o);
            pd0 += __shfl_xor_sync(FULLM, pd0, o);
            pd1 += __shfl_xor_sync(FULLM, pd1, o);
        }
        int gr = row0 + ty * 4 + i;
        if (tx == 0 && gr < n) {
            AS[gr] = make_float2(ps0, ps1);
            AD[gr] = make_float2(pd0, pd1);
        }
    }
}

// ---- layer-1 gather: warp per dst node; fp16 rows, fp32 accumulate, unroll 4 ----
__global__ __launch_bounds__(256)
void gather1_k(const int* __restrict__ rowptr, const int* __restrict__ col,
               const float2* __restrict__ AS, const float2* __restrict__ AD,
               const __half* __restrict__ H, const float* __restrict__ b1,
               float* __restrict__ OUT, int n)
{
    const int lane = threadIdx.x & 31;
    const int i = (blockIdx.x * blockDim.x + threadIdx.x) >> 5;
    if (i >= n) return;
    const bool hs = lane >= 16;               // head1 for cols >= 64
    const float2 adv = AD[i];
    const float ad = hs ? adv.y : adv.x;

    float4 acc = make_float4(0.f, 0.f, 0.f, 0.f);
    float den = 0.f;
    const int beg = rowptr[i], end = rowptr[i + 1];
    #pragma unroll 4
    for (int e = beg; e < end; e++) {
        const int s = __ldg(col + e);
        const float2 asv = __ldg(AS + s);
        float a = (hs ? asv.y : asv.x) + ad;
        a = a > 0.f ? a : NEG_SLOPE * a;
        const float w = __expf(a);
        den += w;
        const uint2 raw = *reinterpret_cast<const uint2*>(H + (size_t)s * 128 + lane * 4);
        const float2 f01 = __half22float2(*reinterpret_cast<const __half2*>(&raw.x));
        const float2 f23 = __half22float2(*reinterpret_cast<const __half2*>(&raw.y));
        acc.x = fmaf(w, f01.x, acc.x); acc.y = fmaf(w, f01.y, acc.y);
        acc.z = fmaf(w, f23.x, acc.z); acc.w = fmaf(w, f23.y, acc.w);
    }
    // self loop
    {
        const float2 asv = AS[i];
        float a = (hs ? asv.y : asv.x) + ad;
        a = a > 0.f ? a : NEG_SLOPE * a;
        const float w = __expf(a);
        den += w;
        const uint2 raw = *reinterpret_cast<const uint2*>(H + (size_t)i * 128 + lane * 4);
        const float2 f01 = __half22float2(*reinterpret_cast<const __half2*>(&raw.x));
        const float2 f23 = __half22float2(*reinterpret_cast<const __half2*>(&raw.y));
        acc.x = fmaf(w, f01.x, acc.x); acc.y = fmaf(w, f01.y, acc.y);
        acc.z = fmaf(w, f23.x, acc.z); acc.w = fmaf(w, f23.y, acc.w);
    }
    const float inv = 1.0f / den;
    const float4 bv = *reinterpret_cast<const float4*>(b1 + lane * 4);
    float4 o;
    o.x = acc.x * inv + bv.x; o.y = acc.y * inv + bv.y;
    o.z = acc.z * inv + bv.z; o.w = acc.w * inv + bv.w;
    *reinterpret_cast<float4*>(OUT + (size_t)i * 128 + lane * 4) = o;
}

// ---- per-column sum / sumsq over agg1 ----
__global__ void bnstats_k(const float* __restrict__ A, float* __restrict__ colsum,
                          float* __restrict__ colsq, int n)
{
    const int c = threadIdx.x;                 // 128 threads
    const int r0 = blockIdx.x * 256;
    const int r1 = min(r0 + 256, n);
    float s = 0.f, q = 0.f;
    for (int r = r0; r < r1; r++) {
        float v = A[(size_t)r * 128 + c];
        s += v; q = fmaf(v, v, q);
    }
    atomicAdd(&colsum[c], s);
    atomicAdd(&colsq[c], q);
}

__global__ void bnfold_k(const float* __restrict__ colsum, const float* __restrict__ colsq,
                         const float* __restrict__ gamma, const float* __restrict__ beta,
                         float* __restrict__ scale, float* __restrict__ shift, int n)
{
    const int t = threadIdx.x;
    float inv_n = 1.0f / (float)n;
    float mean = colsum[t] * inv_n;
    float var  = colsq[t] * inv_n - mean * mean;
    float sc   = gamma[t] * rsqrtf(var + BN_EPS_F);
    scale[t] = sc;
    shift[t] = beta[t] - mean * sc;
}

// ---- layer-2 gather (fp16 rows, unroll 4) + head-mean + bias + log_softmax ----
__global__ __launch_bounds__(256)
void gather2_k(const int* __restrict__ rowptr, const int* __restrict__ col,
               const float2* __restrict__ AS, const float2* __restrict__ AD,
               const __half* __restrict__ H, const float* __restrict__ b2,
               float* __restrict__ out, int n)
{
    const int lane = threadIdx.x & 31;
    const int i = (blockIdx.x * blockDim.x + threadIdx.x) >> 5;
    if (i >= n) return;
    const bool act = lane < 20;               // lane*4 < 80
    const bool hs  = lane >= 10;              // head1 for cols >= 40
    const float2 adv = AD[i];
    const float ad = hs ? adv.y : adv.x;

    float4 acc = make_float4(0.f, 0.f, 0.f, 0.f);
    float den = 0.f;
    const int beg = rowptr[i], end = rowptr[i + 1];
    #pragma unroll 4
    for (int e = beg; e < end; e++) {
        const int s = __ldg(col + e);
        const float2 asv = __ldg(AS + s);
        float a = (hs ? asv.y : asv.x) + ad;
        a = a > 0.f ? a : NEG_SLOPE * a;
        const float w = __expf(a);
        den += w;
        if (act) {
            const uint2 raw = *reinterpret_cast<const uint2*>(H + (size_t)s * 80 + lane * 4);
            const float2 f01 = __half22float2(*reinterpret_cast<const __half2*>(&raw.x));
            const float2 f23 = __half22float2(*reinterpret_cast<const __half2*>(&raw.y));
            acc.x = fmaf(w, f01.x, acc.x); acc.y = fmaf(w, f01.y, acc.y);
            acc.z = fmaf(w, f23.x, acc.z); acc.w = fmaf(w, f23.y, acc.w);
        }
    }
    // self loop
    {
        const float2 asv = AS[i];
        float a = (hs ? asv.y : asv.x) + ad;
        a = a > 0.f ? a : NEG_SLOPE * a;
        const float w = __expf(a);
        den += w;
        if (act) {
            const uint2 raw = *reinterpret_cast<const uint2*>(H + (size_t)i * 80 + lane * 4);
            const float2 f01 = __half22float2(*reinterpret_cast<const __half2*>(&raw.x));
            const float2 f23 = __half22float2(*reinterpret_cast<const __half2*>(&raw.y));
            acc.x = fmaf(w, f01.x, acc.x); acc.y = fmaf(w, f01.y, acc.y);
            acc.z = fmaf(w, f23.x, acc.z); acc.w = fmaf(w, f23.y, acc.w);
        }
    }
    const float inv = 1.0f / den;
    float4 v;
    v.x = acc.x * inv; v.y = acc.y * inv; v.z = acc.z * inv; v.w = acc.w * inv;

    // head mean: lanes 0..9 pair with lanes 10..19
    float4 o;
    o.x = __shfl_sync(FULLM, v.x, lane + 10);
    o.y = __shfl_sync(FULLM, v.y, lane + 10);
    o.z = __shfl_sync(FULLM, v.z, lane + 10);
    o.w = __shfl_sync(FULLM, v.w, lane + 10);

    float4 m = make_float4(-1e30f, -1e30f, -1e30f, -1e30f);
    if (lane < 10) {
        const float4 bv = *reinterpret_cast<const float4*>(b2 + lane * 4);
        m.x = 0.5f * (v.x + o.x) + bv.x;
        m.y = 0.5f * (v.y + o.y) + bv.y;
        m.z = 0.5f * (v.z + o.z) + bv.z;
        m.w = 0.5f * (v.w + o.w) + bv.w;
    }
    float mm = fmaxf(fmaxf(m.x, m.y), fmaxf(m.z, m.w));
    #pragma unroll
    for (int off = 16; off > 0; off >>= 1)
        mm = fmaxf(mm, __shfl_xor_sync(FULLM, mm, off));
    float ssum = 0.f;
    if (lane < 10)
        ssum = __expf(m.x - mm) + __expf(m.y - mm) + __expf(m.z - mm) + __expf(m.w - mm);
    #pragma unroll
    for (int off = 16; off > 0; off >>= 1)
        ssum += __shfl_xor_sync(FULLM, ssum, off);
    const float lse = mm + __logf(ssum);

    if (lane < 10) {
        float4 r;
        r.x = m.x - lse; r.y = m.y - lse; r.z = m.z - lse; r.w = m.w - lse;
        *reinterpret_cast<float4*>(out + (size_t)i * 40 + lane * 4) = r;
    }
}

// ------------------------------- launcher -------------------------------
extern "C" void kernel_launch(void* const* d_in, const int* in_sizes, int n_in,
                              void* d_out, int out_size)
{
    const float* x      = (const float*)d_in[0];
    const int*   ei     = (const int*)  d_in[1];
    const float* W1     = (const float*)d_in[2];
    const float* att_s1 = (const float*)d_in[3];
    const float* att_d1 = (const float*)d_in[4];
    const float* b1     = (const float*)d_in[5];
    const float* gamma  = (const float*)d_in[6];
    const float* beta   = (const float*)d_in[7];
    const float* W2     = (const float*)d_in[8];
    const float* att_s2 = (const float*)d_in[9];
    const float* att_d2 = (const float*)d_in[10];
    const float* b2     = (const float*)d_in[11];
    float* out = (float*)d_out;

    const int n = in_sizes[0] / 128;
    const int E = in_sizes[1] / 2;
    const int* src = ei;
    const int* dst = ei + E;

    float *agg1, *colsum, *colsq, *scale, *shift;
    __half *h1, *h2;
    float2 *as1, *ad1, *as2, *ad2;
    int *deg, *incl, *rowptr, *cursor, *colarr, *bsum;
    cudaGetSymbolAddress((void**)&h1,     g_h1);
    cudaGetSymbolAddress((void**)&agg1,   g_agg1);
    cudaGetSymbolAddress((void**)&h2,     g_h2);
    cudaGetSymbolAddress((void**)&as1,    g_as1);
    cudaGetSymbolAddress((void**)&ad1,    g_ad1);
    cudaGetSymbolAddress((void**)&as2,    g_as2);
    cudaGetSymbolAddress((void**)&ad2,    g_ad2);
    cudaGetSymbolAddress((void**)&deg,    g_deg);
    cudaGetSymbolAddress((void**)&incl,   g_incl);
    cudaGetSymbolAddress((void**)&rowptr, g_rowptr);
    cudaGetSymbolAddress((void**)&cursor, g_cursor);
    cudaGetSymbolAddress((void**)&colarr, g_col);
    cudaGetSymbolAddress((void**)&bsum,   g_bsum);
    cudaGetSymbolAddress((void**)&colsum, g_colsum);
    cudaGetSymbolAddress((void**)&colsq,  g_colsq);
    cudaGetSymbolAddress((void**)&scale,  g_scale);
    cudaGetSymbolAddress((void**)&shift,  g_shift);

    const size_t smem1 = (128 * 128 + 64 * 132) * sizeof(float);  // 99328 B
    const size_t smem2 = (128 * 80  + 64 * 132) * sizeof(float);  // 74752 B
    cudaFuncSetAttribute((const void*)gemm_k<128>, cudaFuncAttributeMaxDynamicSharedMemorySize, (int)smem1);
    cudaFuncSetAttribute((const void*)gemm_k<80>,  cudaFuncAttributeMaxDynamicSharedMemorySize, (int)smem2);

    const int gb = (n + 63) / 64;         // gemm blocks
    const int wb = (n * 32 + 255) / 256;  // warp-per-node blocks
    const int nb = (n + 1023) / 1024;     // scan blocks

    // ---- CSR build (shared by both layers) ----
    zero_init_k<<<(n + 255) / 256, 256>>>(deg, colsum, colsq, n);    // launch 1
    hist_k<<<(E + 255) / 256, 256>>>(dst, deg, E);                   // 2
    scan1_k<<<nb, 1024>>>(deg, incl, bsum, n);                       // 3
    scan3_k<<<(n + 255) / 256, 256>>>(incl, bsum, deg, rowptr, cursor, n, nb); // 4
    fill_k<<<(E + 255) / 256, 256>>>(src, dst, cursor, colarr, E);   // 5

    // ---- layer 1 ----
    gemm_k<128><<<gb, 256, smem1>>>(x, W1, h1, n, nullptr, nullptr,  // 6 <- ncu -s 5 -c 1
                                    att_s1, att_d1, as1, ad1);
    gather1_k<<<wb, 256>>>(rowptr, colarr, as1, ad1, h1, b1, agg1, n);

    // ---- batchnorm stats + fold ----
    bnstats_k<<<(n + 255) / 256, 128>>>(agg1, colsum, colsq, n);
    bnfold_k<<<1, 128>>>(colsum, colsq, gamma, beta, scale, shift, n);

    // ---- layer 2 (BN folded into GEMM A-load) ----
    gemm_k<80><<<gb, 256, smem2>>>(agg1, W2, h2, n, scale, shift,
                                   att_s2, att_d2, as2, ad2);
    gather2_k<<<wb, 256>>>(rowptr, colarr, as2, ad2, h2, b2, out, n);
}

// round 15
// speedup vs baseline: 1.6406x; 1.1019x over previous
#include <cuda_runtime.h>
#include <cuda_fp16.h>
#include <mma.h>

using namespace nvcuda;

#define NEG_SLOPE 0.2f
#define BN_EPS_F  1e-5f
#define FULLM 0xffffffffu

static constexpr int NMAX = 100000;
static constexpr int EMAX = 1700000;

// ---------------- scratch (static device globals; no allocation) ----------------
__device__ __half g_h1  [(size_t)NMAX * 128];   // fp16 activations (gather input only)
__device__ float  g_agg1[(size_t)NMAX * 128];   // fp32 (BN + GEMM2 input)
__device__ __half g_h2  [(size_t)NMAX * 80];
__device__ float2 g_as1 [NMAX];
__device__ float2 g_ad1 [NMAX];
__device__ float2 g_as2 [NMAX];
__device__ float2 g_ad2 [NMAX];
__device__ int    g_deg   [NMAX];
__device__ int    g_incl  [NMAX];
__device__ int    g_rowptr[NMAX + 1];
__device__ int    g_cursor[NMAX];
__device__ int    g_col   [EMAX];
__device__ int    g_bsum  [256];
__device__ float  g_colsum[128];
__device__ float  g_colsq [128];
__device__ float  g_scale [128];
__device__ float  g_shift [128];

// ---------------- CSR build ----------------
__global__ void zero_init_k(int* deg, float* colsum, float* colsq, int n) {
    int i = blockIdx.x * blockDim.x + threadIdx.x;
    if (i < n) deg[i] = 0;
    if (i < 128) { colsum[i] = 0.f; colsq[i] = 0.f; }
}

__global__ void hist_k(const int* __restrict__ dst, int* __restrict__ deg, int E) {
    int e = blockIdx.x * blockDim.x + threadIdx.x;
    if (e < E) atomicAdd(&deg[dst[e]], 1);
}

// per-block (1024) inclusive scan + block sums
__global__ void scan1_k(const int* __restrict__ deg, int* __restrict__ incl,
                        int* __restrict__ bsum, int n) {
    __shared__ int wsum[32];
    const int tid = threadIdx.x;
    const int gid = blockIdx.x * 1024 + tid;
    const int lane = tid & 31, w = tid >> 5;
    int x = (gid < n) ? deg[gid] : 0;
    #pragma unroll
    for (int o = 1; o < 32; o <<= 1) {
        int t = __shfl_up_sync(FULLM, x, o);
        if (lane >= o) x += t;
    }
    if (lane == 31) wsum[w] = x;
    __syncthreads();
    if (w == 0) {
        int y = wsum[lane];
        #pragma unroll
        for (int o = 1; o < 32; o <<= 1) {
            int t = __shfl_up_sync(FULLM, y, o);
            if (lane >= o) y += t;
        }
        wsum[lane] = y;
    }
    __syncthreads();
    if (w > 0) x += wsum[w - 1];
    if (gid < n) incl[gid] = x;
    if (tid == 1023) bsum[blockIdx.x] = x;
}

// rowptr + cursor; each block redundantly exclusive-scans bsum (<=128 vals) in smem
__global__ void scan3_k(const int* __restrict__ incl, const int* __restrict__ bsum,
                        const int* __restrict__ deg, int* __restrict__ rowptr,
                        int* __restrict__ cursor, int n, int nb) {
    __shared__ int pre[128];
    __shared__ int ws[4];
    const int tid = threadIdx.x;
    if (tid < 128) {
        const int lane = tid & 31, w = tid >> 5;
        int orig = (tid < nb) ? bsum[tid] : 0;
        int x = orig;
        #pragma unroll
        for (int o = 1; o < 32; o <<= 1) {
            int t = __shfl_up_sync(FULLM, x, o);
            if (lane >= o) x += t;
        }
        if (lane == 31) ws[w] = x;
        __syncwarp();
        pre[tid] = x - orig;   // exclusive within warp
    }
    __syncthreads();
    if (tid < 128) {
        const int w = tid >> 5;
        int add = 0;
        #pragma unroll
        for (int k = 0; k < 4; k++) if (k < w) add += ws[k];
        pre[tid] += add;       // exclusive across all 128
    }
    __syncthreads();

    int i = blockIdx.x * blockDim.x + tid;
    if (i < n) {
        int v = incl[i] + pre[i >> 10];
        rowptr[i + 1] = v;
        cursor[i] = v - deg[i];
    }
    if (i == 0) rowptr[0] = 0;
}

__global__ void fill_k(const int* __restrict__ src, const int* __restrict__ dst,
                       int* __restrict__ cursor, int* __restrict__ col, int E) {
    int e = blockIdx.x * blockDim.x + threadIdx.x;
    if (e < E) {
        int p = atomicAdd(&cursor[dst[e]], 1);
        col[p] = src[e];
    }
}

// ---- GEMM via fp16 wmma (HMMA, fp32 accum): H[n,NOUT](fp16) = X[n,128]@W[128,NOUT]
//      Optional BN fold on X load; fused AS/AD attention epilogue from fp32 smem. ----
template<int NOUT>
__global__ __launch_bounds__(256, 2)
void gemm_k(const float* __restrict__ X, const float* __restrict__ W,
            __half* __restrict__ H, int n,
            const float* __restrict__ scale, const float* __restrict__ shift,
            const float* __restrict__ attS, const float* __restrict__ attD,
            float2* __restrict__ AS, float2* __restrict__ AD)
{
    constexpr int TN = (NOUT == 128) ? 8 : 5;
    constexpr int HALF = NOUT / 2;
    constexpr int LDO = NOUT + 8;            // padded fp32 out stride

    extern __shared__ char smemc[];
    __half* sWh = reinterpret_cast<__half*>(smemc);                    // [128*NOUT]
    __half* sXh = reinterpret_cast<__half*>(smemc + 128 * NOUT * 2);   // [64*128]
    float*  sO  = reinterpret_cast<float*>(smemc + 128 * NOUT * 2 + 64 * 128 * 2); // [64*LDO]

    const int tid = threadIdx.x;
    const int row0 = blockIdx.x * 64;
    const bool bn = (scale != nullptr);

    for (int i = tid; i < 128 * NOUT; i += 256) sWh[i] = __float2half_rn(W[i]);
    for (int i = tid; i < 64 * 128; i += 256) {
        int r = i >> 7, c = i & 127;
        int gr = row0 + r;
        float v = (gr < n) ? X[(size_t)gr * 128 + c] : 0.0f;
        if (bn) v = fmaf(v, scale[c], shift[c]);
        sXh[r * 128 + c] = __float2half_rn(v);
    }
    __syncthreads();

    // 8 warps: 4 row strips x 2 col halves (compile-time trip counts per half)
    {
        const int warp = tid >> 5;
        const int rs = warp >> 1;            // row strip 0..3 (16 rows each)
        const int ch = warp & 1;             // col half

        if constexpr (NOUT == 128) {
            const int ct0 = ch * 4;
            wmma::fragment<wmma::accumulator, 16, 16, 16, float> accf[4];
            #pragma unroll
            for (int t = 0; t < 4; t++) wmma::fill_fragment(accf[t], 0.0f);
            #pragma unroll
            for (int k = 0; k < 8; k++) {
                wmma::fragment<wmma::matrix_a, 16, 16, 16, __half, wmma::row_major> af;
                wmma::load_matrix_sync(af, sXh + rs * 16 * 128 + k * 16, 128);
                #pragma unroll
                for (int t = 0; t < 4; t++) {
                    wmma::fragment<wmma::matrix_b, 16, 16, 16, __half, wmma::row_major> bf;
                    wmma::load_matrix_sync(bf, sWh + k * 16 * 128 + (ct0 + t) * 16, 128);
                    wmma::mma_sync(accf[t], af, bf, accf[t]);
                }
            }
            #pragma unroll
            for (int t = 0; t < 4; t++)
                wmma::store_matrix_sync(sO + rs * 16 * LDO + (ct0 + t) * 16, accf[t],
                                        LDO, wmma::mem_row_major);
        } else {
            // NOUT=80: half 0 -> tiles 0..2, half 1 -> tiles 3..4
            if (ch == 0) {
                wmma::fragment<wmma::accumulator, 16, 16, 16, float> accf[3];
                #pragma unroll
                for (int t = 0; t < 3; t++) wmma::fill_fragment(accf[t], 0.0f);
                #pragma unroll
                for (int k = 0; k < 8; k++) {
                    wmma::fragment<wmma::matrix_a, 16, 16, 16, __half, wmma::row_major> af;
                    wmma::load_matrix_sync(af, sXh + rs * 16 * 128 + k * 16, 128);
                    #pragma unroll
                    for (int t = 0; t < 3; t++) {
                        wmma::fragment<wmma::matrix_b, 16, 16, 16, __half, wmma::row_major> bf;
                        wmma::load_matrix_sync(bf, sWh + k * 16 * 80 + t * 16, 80);
                        wmma::mma_sync(accf[t], af, bf, accf[t]);
                    }
                }
                #pragma unroll
                for (int t = 0; t < 3; t++)
                    wmma::store_matrix_sync(sO + rs * 16 * LDO + t * 16, accf[t],
                                            LDO, wmma::mem_row_major);
            } else {
                wmma::fragment<wmma::accumulator, 16, 16, 16, float> accf[2];
                #pragma unroll
                for (int t = 0; t < 2; t++) wmma::fill_fragment(accf[t], 0.0f);
                #pragma unroll
                for (int k = 0; k < 8; k++) {
                    wmma::fragment<wmma::matrix_a, 16, 16, 16, __half, wmma::row_major> af;
                    wmma::load_matrix_sync(af, sXh + rs * 16 * 128 + k * 16, 128);
                    #pragma unroll
                    for (int t = 0; t < 2; t++) {
                        wmma::fragment<wmma::matrix_b, 16, 16, 16, __half, wmma::row_major> bf;
                        wmma::load_matrix_sync(bf, sWh + k * 16 * 80 + (3 + t) * 16, 80);
                        wmma::mma_sync(accf[t], af, bf, accf[t]);
                    }
                }
                #pragma unroll
                for (int t = 0; t < 2; t++)
                    wmma::store_matrix_sync(sO + rs * 16 * LDO + (3 + t) * 16, accf[t],
                                            LDO, wmma::mem_row_major);
            }
        }
    }
    __syncthreads();

    // ---- epilogue (same structure as FFMA version, reading fp32 from sO) ----
    const int tx = tid & 15;
    const int ty = tid >> 4;

    int cmap[TN];
    #pragma unroll
    for (int j = 0; j < TN; j++) {
        if constexpr (NOUT == 128) cmap[j] = tx * 8 + j;
        else cmap[j] = (j < 4) ? (tx * 4 + j) : (64 + tx);
    }

    float acc[4][TN];
    #pragma unroll
    for (int i = 0; i < 4; i++) {
        const float* rowp = sO + (ty * 4 + i) * LDO;
        #pragma unroll
        for (int j = 0; j < TN; j++) acc[i][j] = rowp[cmap[j]];
    }

    // store H as fp16 (vectorized)
    #pragma unroll
    for (int i = 0; i < 4; i++) {
        int gr = row0 + ty * 4 + i;
        if (gr < n) {
            if constexpr (NOUT == 128) {
                __half2 h0 = __floats2half2_rn(acc[i][0], acc[i][1]);
                __half2 h1v = __floats2half2_rn(acc[i][2], acc[i][3]);
                __half2 h2v = __floats2half2_rn(acc[i][4], acc[i][5]);
                __half2 h3 = __floats2half2_rn(acc[i][6], acc[i][7]);
                uint4 pkt;
                pkt.x = *reinterpret_cast<unsigned int*>(&h0);
                pkt.y = *reinterpret_cast<unsigned int*>(&h1v);
                pkt.z = *reinterpret_cast<unsigned int*>(&h2v);
                pkt.w = *reinterpret_cast<unsigned int*>(&h3);
                *reinterpret_cast<uint4*>(H + (size_t)gr * 128 + tx * 8) = pkt;
            } else {
                __half2 h0 = __floats2half2_rn(acc[i][0], acc[i][1]);
                __half2 h1v = __floats2half2_rn(acc[i][2], acc[i][3]);
                uint2 pkt;
                pkt.x = *reinterpret_cast<unsigned int*>(&h0);
                pkt.y = *reinterpret_cast<unsigned int*>(&h1v);
                *reinterpret_cast<uint2*>(H + (size_t)gr * 80 + tx * 4) = pkt;
                H[(size_t)gr * 80 + 64 + tx] = __float2half_rn(acc[i][4]);
            }
        }
    }

    // fused attention dot products (fp32), per head, 16-lane reduce
    float av[TN], dv[TN];
    #pragma unroll
    for (int j = 0; j < TN; j++) {
        av[j] = attS[cmap[j]];
        dv[j] = attD[cmap[j]];
    }
    #pragma unroll
    for (int i = 0; i < 4; i++) {
        float ps0 = 0.f, ps1 = 0.f, pd0 = 0.f, pd1 = 0.f;
        #pragma unroll
        for (int j = 0; j < TN; j++) {
            if (cmap[j] < HALF) {
                ps0 = fmaf(acc[i][j], av[j], ps0);
                pd0 = fmaf(acc[i][j], dv[j], pd0);
            } else {
                ps1 = fmaf(acc[i][j], av[j], ps1);
                pd1 = fmaf(acc[i][j], dv[j], pd1);
            }
        }
        #pragma unroll
        for (int o = 1; o < 16; o <<= 1) {
            ps0 += __shfl_xor_sync(FULLM, ps0, o);
            ps1 += __shfl_xor_sync(FULLM, ps1, o);
            pd0 += __shfl_xor_sync(FULLM, pd0, o);
            pd1 += __shfl_xor_sync(FULLM, pd1, o);
        }
        int gr = row0 + ty * 4 + i;
        if (tx == 0 && gr < n) {
            AS[gr] = make_float2(ps0, ps1);
            AD[gr] = make_float2(pd0, pd1);
        }
    }
}

// ---- layer-1 gather: warp per dst node; fp16 rows, fp32 accumulate, unroll 4 ----
__global__ __launch_bounds__(256)
void gather1_k(const int* __restrict__ rowptr, const int* __restrict__ col,
               const float2* __restrict__ AS, const float2* __restrict__ AD,
               const __half* __restrict__ H, const float* __restrict__ b1,
               float* __restrict__ OUT, int n)
{
    const int lane = threadIdx.x & 31;
    const int i = (blockIdx.x * blockDim.x + threadIdx.x) >> 5;
    if (i >= n) return;
    const bool hs = lane >= 16;               // head1 for cols >= 64
    const float2 adv = AD[i];
    const float ad = hs ? adv.y : adv.x;

    float4 acc = make_float4(0.f, 0.f, 0.f, 0.f);
    float den = 0.f;
    const int beg = rowptr[i], end = rowptr[i + 1];
    #pragma unroll 4
    for (int e = beg; e < end; e++) {
        const int s = __ldg(col + e);
        const float2 asv = __ldg(AS + s);
        float a = (hs ? asv.y : asv.x) + ad;
        a = a > 0.f ? a : NEG_SLOPE * a;
        const float w = __expf(a);
        den += w;
        const uint2 raw = *reinterpret_cast<const uint2*>(H + (size_t)s * 128 + lane * 4);
        const float2 f01 = __half22float2(*reinterpret_cast<const __half2*>(&raw.x));
        const float2 f23 = __half22float2(*reinterpret_cast<const __half2*>(&raw.y));
        acc.x = fmaf(w, f01.x, acc.x); acc.y = fmaf(w, f01.y, acc.y);
        acc.z = fmaf(w, f23.x, acc.z); acc.w = fmaf(w, f23.y, acc.w);
    }
    // self loop
    {
        const float2 asv = AS[i];
        float a = (hs ? asv.y : asv.x) + ad;
        a = a > 0.f ? a : NEG_SLOPE * a;
        const float w = __expf(a);
        den += w;
        const uint2 raw = *reinterpret_cast<const uint2*>(H + (size_t)i * 128 + lane * 4);
        const float2 f01 = __half22float2(*reinterpret_cast<const __half2*>(&raw.x));
        const float2 f23 = __half22float2(*reinterpret_cast<const __half2*>(&raw.y));
        acc.x = fmaf(w, f01.x, acc.x); acc.y = fmaf(w, f01.y, acc.y);
        acc.z = fmaf(w, f23.x, acc.z); acc.w = fmaf(w, f23.y, acc.w);
    }
    const float inv = 1.0f / den;
    const float4 bv = *reinterpret_cast<const float4*>(b1 + lane * 4);
    float4 o;
    o.x = acc.x * inv + bv.x; o.y = acc.y * inv + bv.y;
    o.z = acc.z * inv + bv.z; o.w = acc.w * inv + bv.w;
    *reinterpret_cast<float4*>(OUT + (size_t)i * 128 + lane * 4) = o;
}

// ---- per-column sum / sumsq over agg1 ----
__global__ void bnstats_k(const float* __restrict__ A, float* __restrict__ colsum,
                          float* __restrict__ colsq, int n)
{
    const int c = threadIdx.x;                 // 128 threads
    const int r0 = blockIdx.x * 256;
    const int r1 = min(r0 + 256, n);
    float s = 0.f, q = 0.f;
    for (int r = r0; r < r1; r++) {
        float v = A[(size_t)r * 128 + c];
        s += v; q = fmaf(v, v, q);
    }
    atomicAdd(&colsum[c], s);
    atomicAdd(&colsq[c], q);
}

__global__ void bnfold_k(const float* __restrict__ colsum, const float* __restrict__ colsq,
                         const float* __restrict__ gamma, const float* __restrict__ beta,
                         float* __restrict__ scale, float* __restrict__ shift, int n)
{
    const int t = threadIdx.x;
    float inv_n = 1.0f / (float)n;
    float mean = colsum[t] * inv_n;
    float var  = colsq[t] * inv_n - mean * mean;
    float sc   = gamma[t] * rsqrtf(var + BN_EPS_F);
    scale[t] = sc;
    shift[t] = beta[t] - mean * sc;
}

// ---- layer-2 gather (fp16 rows, unroll 4) + head-mean + bias + log_softmax ----
__global__ __launch_bounds__(256)
void gather2_k(const int* __restrict__ rowptr, const int* __restrict__ col,
               const float2* __restrict__ AS, const float2* __restrict__ AD,
               const __half* __restrict__ H, const float* __restrict__ b2,
               float* __restrict__ out, int n)
{
    const int lane = threadIdx.x & 31;
    const int i = (blockIdx.x * blockDim.x + threadIdx.x) >> 5;
    if (i >= n) return;
    const bool act = lane < 20;               // lane*4 < 80
    const bool hs  = lane >= 10;              // head1 for cols >= 40
    const float2 adv = AD[i];
    const float ad = hs ? adv.y : adv.x;

    float4 acc = make_float4(0.f, 0.f, 0.f, 0.f);
    float den = 0.f;
    const int beg = rowptr[i], end = rowptr[i + 1];
    #pragma unroll 4
    for (int e = beg; e < end; e++) {
        const int s = __ldg(col + e);
        const float2 asv = __ldg(AS + s);
        float a = (hs ? asv.y : asv.x) + ad;
        a = a > 0.f ? a : NEG_SLOPE * a;
        const float w = __expf(a);
        den += w;
        if (act) {
            const uint2 raw = *reinterpret_cast<const uint2*>(H + (size_t)s * 80 + lane * 4);
            const float2 f01 = __half22float2(*reinterpret_cast<const __half2*>(&raw.x));
            const float2 f23 = __half22float2(*reinterpret_cast<const __half2*>(&raw.y));
            acc.x = fmaf(w, f01.x, acc.x); acc.y = fmaf(w, f01.y, acc.y);
            acc.z = fmaf(w, f23.x, acc.z); acc.w = fmaf(w, f23.y, acc.w);
        }
    }
    // self loop
    {
        const float2 asv = AS[i];
        float a = (hs ? asv.y : asv.x) + ad;
        a = a > 0.f ? a : NEG_SLOPE * a;
        const float w = __expf(a);
        den += w;
        if (act) {
            const uint2 raw = *reinterpret_cast<const uint2*>(H + (size_t)i * 80 + lane * 4);
            const float2 f01 = __half22float2(*reinterpret_cast<const __half2*>(&raw.x));
            const float2 f23 = __half22float2(*reinterpret_cast<const __half2*>(&raw.y));
            acc.x = fmaf(w, f01.x, acc.x); acc.y = fmaf(w, f01.y, acc.y);
            acc.z = fmaf(w, f23.x, acc.z); acc.w = fmaf(w, f23.y, acc.w);
        }
    }
    const float inv = 1.0f / den;
    float4 v;
    v.x = acc.x * inv; v.y = acc.y * inv; v.z = acc.z * inv; v.w = acc.w * inv;

    // head mean: lanes 0..9 pair with lanes 10..19
    float4 o;
    o.x = __shfl_sync(FULLM, v.x, lane + 10);
    o.y = __shfl_sync(FULLM, v.y, lane + 10);
    o.z = __shfl_sync(FULLM, v.z, lane + 10);
    o.w = __shfl_sync(FULLM, v.w, lane + 10);

    float4 m = make_float4(-1e30f, -1e30f, -1e30f, -1e30f);
    if (lane < 10) {
        const float4 bv = *reinterpret_cast<const float4*>(b2 + lane * 4);
        m.x = 0.5f * (v.x + o.x) + bv.x;
        m.y = 0.5f * (v.y + o.y) + bv.y;
        m.z = 0.5f * (v.z + o.z) + bv.z;
        m.w = 0.5f * (v.w + o.w) + bv.w;
    }
    float mm = fmaxf(fmaxf(m.x, m.y), fmaxf(m.z, m.w));
    #pragma unroll
    for (int off = 16; off > 0; off >>= 1)
        mm = fmaxf(mm, __shfl_xor_sync(FULLM, mm, off));
    float ssum = 0.f;
    if (lane < 10)
        ssum = __expf(m.x - mm) + __expf(m.y - mm) + __expf(m.z - mm) + __expf(m.w - mm);
    #pragma unroll
    for (int off = 16; off > 0; off >>= 1)
        ssum += __shfl_xor_sync(FULLM, ssum, off);
    const float lse = mm + __logf(ssum);

    if (lane < 10) {
        float4 r;
        r.x = m.x - lse; r.y = m.y - lse; r.z = m.z - lse; r.w = m.w - lse;
        *reinterpret_cast<float4*>(out + (size_t)i * 40 + lane * 4) = r;
    }
}

// ------------------------------- launcher -------------------------------
extern "C" void kernel_launch(void* const* d_in, const int* in_sizes, int n_in,
                              void* d_out, int out_size)
{
    const float* x      = (const float*)d_in[0];
    const int*   ei     = (const int*)  d_in[1];
    const float* W1     = (const float*)d_in[2];
    const float* att_s1 = (const float*)d_in[3];
    const float* att_d1 = (const float*)d_in[4];
    const float* b1     = (const float*)d_in[5];
    const float* gamma  = (const float*)d_in[6];
    const float* beta   = (const float*)d_in[7];
    const float* W2     = (const float*)d_in[8];
    const float* att_s2 = (const float*)d_in[9];
    const float* att_d2 = (const float*)d_in[10];
    const float* b2     = (const float*)d_in[11];
    float* out = (float*)d_out;

    const int n = in_sizes[0] / 128;
    const int E = in_sizes[1] / 2;
    const int* src = ei;
    const int* dst = ei + E;

    float *agg1, *colsum, *colsq, *scale, *shift;
    __half *h1, *h2;
    float2 *as1, *ad1, *as2, *ad2;
    int *deg, *incl, *rowptr, *cursor, *colarr, *bsum;
    cudaGetSymbolAddress((void**)&h1,     g_h1);
    cudaGetSymbolAddress((void**)&agg1,   g_agg1);
    cudaGetSymbolAddress((void**)&h2,     g_h2);
    cudaGetSymbolAddress((void**)&as1,    g_as1);
    cudaGetSymbolAddress((void**)&ad1,    g_ad1);
    cudaGetSymbolAddress((void**)&as2,    g_as2);
    cudaGetSymbolAddress((void**)&ad2,    g_ad2);
    cudaGetSymbolAddress((void**)&deg,    g_deg);
    cudaGetSymbolAddress((void**)&incl,   g_incl);
    cudaGetSymbolAddress((void**)&rowptr, g_rowptr);
    cudaGetSymbolAddress((void**)&cursor, g_cursor);
    cudaGetSymbolAddress((void**)&colarr, g_col);
    cudaGetSymbolAddress((void**)&bsum,   g_bsum);
    cudaGetSymbolAddress((void**)&colsum, g_colsum);
    cudaGetSymbolAddress((void**)&colsq,  g_colsq);
    cudaGetSymbolAddress((void**)&scale,  g_scale);
    cudaGetSymbolAddress((void**)&shift,  g_shift);

    // smem: W fp16 + X fp16 + out fp32(padded)
    const size_t smem1 = (size_t)128 * 128 * 2 + 64 * 128 * 2 + 64 * 136 * 4; // 83968
    const size_t smem2 = (size_t)128 * 80  * 2 + 64 * 128 * 2 + 64 * 88  * 4; // 59392
    cudaFuncSetAttribute((const void*)gemm_k<128>, cudaFuncAttributeMaxDynamicSharedMemorySize, (int)smem1);
    cudaFuncSetAttribute((const void*)gemm_k<80>,  cudaFuncAttributeMaxDynamicSharedMemorySize, (int)smem2);

    const int gb = (n + 63) / 64;         // gemm blocks
    const int wb = (n * 32 + 255) / 256;  // warp-per-node blocks
    const int nb = (n + 1023) / 1024;     // scan blocks

    // ---- CSR build (shared by both layers) ----
    zero_init_k<<<(n + 255) / 256, 256>>>(deg, colsum, colsq, n);    // launch 1
    hist_k<<<(E + 255) / 256, 256>>>(dst, deg, E);                   // 2
    scan1_k<<<nb, 1024>>>(deg, incl, bsum, n);                       // 3
    scan3_k<<<(n + 255) / 256, 256>>>(incl, bsum, deg, rowptr, cursor, n, nb); // 4
    fill_k<<<(E + 255) / 256, 256>>>(src, dst, cursor, colarr, E);   // 5

    // ---- layer 1 ----
    gemm_k<128><<<gb, 256, smem1>>>(x, W1, h1, n, nullptr, nullptr,  // 6 <- ncu window
                                    att_s1, att_d1, as1, ad1);
    gather1_k<<<wb, 256>>>(rowptr, colarr, as1, ad1, h1, b1, agg1, n);

    // ---- batchnorm stats + fold ----
    bnstats_k<<<(n + 255) / 256, 128>>>(agg1, colsum, colsq, n);
    bnfold_k<<<1, 128>>>(colsum, colsq, gamma, beta, scale, shift, n);

    // ---- layer 2 (BN folded into GEMM A-load) ----
    gemm_k<80><<<gb, 256, smem2>>>(agg1, W2, h2, n, scale, shift,
                                   att_s2, att_d2, as2, ad2);
    gather2_k<<<wb, 256>>>(rowptr, colarr, as2, ad2, h2, b2, out, n);
}

// round 17
// speedup vs baseline: 1.6700x; 1.0180x over previous
#include <cuda_runtime.h>
#include <cuda_fp16.h>
#include <mma.h>

using namespace nvcuda;

#define NEG_SLOPE 0.2f
#define BN_EPS_F  1e-5f
#define FULLM 0xffffffffu

static constexpr int NMAX = 100000;
static constexpr int EMAX = 1700000;

// ---------------- scratch (static device globals; no allocation) ----------------
__device__ __half g_h1  [(size_t)NMAX * 128];   // fp16 activations (gather input only)
__device__ __half g_agg1[(size_t)NMAX * 128];   // fp16 (BN stats + GEMM2 input)
__device__ __half g_h2  [(size_t)NMAX * 80];
__device__ float2 g_as1 [NMAX];
__device__ float2 g_ad1 [NMAX];
__device__ float2 g_as2 [NMAX];
__device__ float2 g_ad2 [NMAX];
__device__ int    g_deg   [NMAX];
__device__ int    g_incl  [NMAX];
__device__ int    g_rowptr[NMAX + 1];
__device__ int    g_cursor[NMAX];
__device__ int    g_col   [EMAX];
__device__ int    g_bsum  [256];
__device__ float  g_colsum[128];
__device__ float  g_colsq [128];
__device__ float  g_scale [128];
__device__ float  g_shift [128];

__device__ __forceinline__ float ld_as_float(const float* p)  { return *p; }
__device__ __forceinline__ float ld_as_float(const __half* p) { return __half2float(*p); }

// ---------------- CSR build ----------------
__global__ void zero_init_k(int* deg, float* colsum, float* colsq, int n) {
    int i = blockIdx.x * blockDim.x + threadIdx.x;
    if (i < n) deg[i] = 0;
    if (i < 128) { colsum[i] = 0.f; colsq[i] = 0.f; }
}

__global__ void hist_k(const int* __restrict__ dst, int* __restrict__ deg, int E) {
    int e = blockIdx.x * blockDim.x + threadIdx.x;
    if (e < E) atomicAdd(&deg[dst[e]], 1);
}

// per-block (1024) inclusive scan + block sums
__global__ void scan1_k(const int* __restrict__ deg, int* __restrict__ incl,
                        int* __restrict__ bsum, int n) {
    __shared__ int wsum[32];
    const int tid = threadIdx.x;
    const int gid = blockIdx.x * 1024 + tid;
    const int lane = tid & 31, w = tid >> 5;
    int x = (gid < n) ? deg[gid] : 0;
    #pragma unroll
    for (int o = 1; o < 32; o <<= 1) {
        int t = __shfl_up_sync(FULLM, x, o);
        if (lane >= o) x += t;
    }
    if (lane == 31) wsum[w] = x;
    __syncthreads();
    if (w == 0) {
        int y = wsum[lane];
        #pragma unroll
        for (int o = 1; o < 32; o <<= 1) {
            int t = __shfl_up_sync(FULLM, y, o);
            if (lane >= o) y += t;
        }
        wsum[lane] = y;
    }
    __syncthreads();
    if (w > 0) x += wsum[w - 1];
    if (gid < n) incl[gid] = x;
    if (tid == 1023) bsum[blockIdx.x] = x;
}

// rowptr + cursor; each block redundantly exclusive-scans bsum (<=128 vals) in smem
__global__ void scan3_k(const int* __restrict__ incl, const int* __restrict__ bsum,
                        const int* __restrict__ deg, int* __restrict__ rowptr,
                        int* __restrict__ cursor, int n, int nb) {
    __shared__ int pre[128];
    __shared__ int ws[4];
    const int tid = threadIdx.x;
    if (tid < 128) {
        const int lane = tid & 31, w = tid >> 5;
        int orig = (tid < nb) ? bsum[tid] : 0;
        int x = orig;
        #pragma unroll
        for (int o = 1; o < 32; o <<= 1) {
            int t = __shfl_up_sync(FULLM, x, o);
            if (lane >= o) x += t;
        }
        if (lane == 31) ws[w] = x;
        __syncwarp();
        pre[tid] = x - orig;   // exclusive within warp
    }
    __syncthreads();
    if (tid < 128) {
        const int w = tid >> 5;
        int add = 0;
        #pragma unroll
        for (int k = 0; k < 4; k++) if (k < w) add += ws[k];
        pre[tid] += add;       // exclusive across all 128
    }
    __syncthreads();

    int i = blockIdx.x * blockDim.x + tid;
    if (i < n) {
        int v = incl[i] + pre[i >> 10];
        rowptr[i + 1] = v;
        cursor[i] = v - deg[i];
    }
    if (i == 0) rowptr[0] = 0;
}

__global__ void fill_k(const int* __restrict__ src, const int* __restrict__ dst,
                       int* __restrict__ cursor, int* __restrict__ col, int E) {
    int e = blockIdx.x * blockDim.x + threadIdx.x;
    if (e < E) {
        int p = atomicAdd(&cursor[dst[e]], 1);
        col[p] = src[e];
    }
}

// ---- GEMM via fp16 wmma (HMMA, fp32 accum): H[n,NOUT](fp16) = X[n,128]@W[128,NOUT]
//      TIN = float (layer 1) or __half (layer 2). Optional BN fold on X load;
//      fused AS/AD attention epilogue from fp32 smem. ----
template<int NOUT, typename TIN>
__global__ __launch_bounds__(256, 2)
void gemm_k(const TIN* __restrict__ X, const float* __restrict__ W,
            __half* __restrict__ H, int n,
            const float* __restrict__ scale, const float* __restrict__ shift,
            const float* __restrict__ attS, const float* __restrict__ attD,
            float2* __restrict__ AS, float2* __restrict__ AD)
{
    constexpr int TN = (NOUT == 128) ? 8 : 5;
    constexpr int HALF = NOUT / 2;
    constexpr int LDO = NOUT + 8;            // padded fp32 out stride

    extern __shared__ char smemc[];
    __half* sWh = reinterpret_cast<__half*>(smemc);                    // [128*NOUT]
    __half* sXh = reinterpret_cast<__half*>(smemc + 128 * NOUT * 2);   // [64*128]
    float*  sO  = reinterpret_cast<float*>(smemc + 128 * NOUT * 2 + 64 * 128 * 2); // [64*LDO]

    const int tid = threadIdx.x;
    const int row0 = blockIdx.x * 64;
    const bool bn = (scale != nullptr);

    for (int i = tid; i < 128 * NOUT; i += 256) sWh[i] = __float2half_rn(W[i]);
    for (int i = tid; i < 64 * 128; i += 256) {
        int r = i >> 7, c = i & 127;
        int gr = row0 + r;
        float v = (gr < n) ? ld_as_float(X + (size_t)gr * 128 + c) : 0.0f;
        if (bn) v = fmaf(v, scale[c], shift[c]);
        sXh[r * 128 + c] = __float2half_rn(v);
    }
    __syncthreads();

    // 8 warps: 4 row strips x 2 col halves (compile-time trip counts per half)
    {
        const int warp = tid >> 5;
        const int rs = warp >> 1;            // row strip 0..3 (16 rows each)
        const int ch = warp & 1;             // col half

        if constexpr (NOUT == 128) {
            const int ct0 = ch * 4;
            wmma::fragment<wmma::accumulator, 16, 16, 16, float> accf[4];
            #pragma unroll
            for (int t = 0; t < 4; t++) wmma::fill_fragment(accf[t], 0.0f);
            #pragma unroll
            for (int k = 0; k < 8; k++) {
                wmma::fragment<wmma::matrix_a, 16, 16, 16, __half, wmma::row_major> af;
                wmma::load_matrix_sync(af, sXh + rs * 16 * 128 + k * 16, 128);
                #pragma unroll
                for (int t = 0; t < 4; t++) {
                    wmma::fragment<wmma::matrix_b, 16, 16, 16, __half, wmma::row_major> bf;
                    wmma::load_matrix_sync(bf, sWh + k * 16 * 128 + (ct0 + t) * 16, 128);
                    wmma::mma_sync(accf[t], af, bf, accf[t]);
                }
            }
            #pragma unroll
            for (int t = 0; t < 4; t++)
                wmma::store_matrix_sync(sO + rs * 16 * LDO + (ct0 + t) * 16, accf[t],
                                        LDO, wmma::mem_row_major);
        } else {
            if (ch == 0) {
                wmma::fragment<wmma::accumulator, 16, 16, 16, float> accf[3];
                #pragma unroll
                for (int t = 0; t < 3; t++) wmma::fill_fragment(accf[t], 0.0f);
                #pragma unroll
                for (int k = 0; k < 8; k++) {
                    wmma::fragment<wmma::matrix_a, 16, 16, 16, __half, wmma::row_major> af;
                    wmma::load_matrix_sync(af, sXh + rs * 16 * 128 + k * 16, 128);
                    #pragma unroll
                    for (int t = 0; t < 3; t++) {
                        wmma::fragment<wmma::matrix_b, 16, 16, 16, __half, wmma::row_major> bf;
                        wmma::load_matrix_sync(bf, sWh + k * 16 * 80 + t * 16, 80);
                        wmma::mma_sync(accf[t], af, bf, accf[t]);
                    }
                }
                #pragma unroll
                for (int t = 0; t < 3; t++)
                    wmma::store_matrix_sync(sO + rs * 16 * LDO + t * 16, accf[t],
                                            LDO, wmma::mem_row_major);
            } else {
                wmma::fragment<wmma::accumulator, 16, 16, 16, float> accf[2];
                #pragma unroll
                for (int t = 0; t < 2; t++) wmma::fill_fragment(accf[t], 0.0f);
                #pragma unroll
                for (int k = 0; k < 8; k++) {
                    wmma::fragment<wmma::matrix_a, 16, 16, 16, __half, wmma::row_major> af;
                    wmma::load_matrix_sync(af, sXh + rs * 16 * 128 + k * 16, 128);
                    #pragma unroll
                    for (int t = 0; t < 2; t++) {
                        wmma::fragment<wmma::matrix_b, 16, 16, 16, __half, wmma::row_major> bf;
                        wmma::load_matrix_sync(bf, sWh + k * 16 * 80 + (3 + t) * 16, 80);
                        wmma::mma_sync(accf[t], af, bf, accf[t]);
                    }
                }
                #pragma unroll
                for (int t = 0; t < 2; t++)
                    wmma::store_matrix_sync(sO + rs * 16 * LDO + (3 + t) * 16, accf[t],
                                            LDO, wmma::mem_row_major);
            }
        }
    }
    __syncthreads();

    // ---- epilogue: fp16 H store + fused fp32 attention dots ----
    const int tx = tid & 15;
    const int ty = tid >> 4;

    int cmap[TN];
    #pragma unroll
    for (int j = 0; j < TN; j++) {
        if constexpr (NOUT == 128) cmap[j] = tx * 8 + j;
        else cmap[j] = (j < 4) ? (tx * 4 + j) : (64 + tx);
    }

    float acc[4][TN];
    #pragma unroll
    for (int i = 0; i < 4; i++) {
        const float* rowp = sO + (ty * 4 + i) * LDO;
        #pragma unroll
        for (int j = 0; j < TN; j++) acc[i][j] = rowp[cmap[j]];
    }

    #pragma unroll
    for (int i = 0; i < 4; i++) {
        int gr = row0 + ty * 4 + i;
        if (gr < n) {
            if constexpr (NOUT == 128) {
                __half2 h0 = __floats2half2_rn(acc[i][0], acc[i][1]);
                __half2 h1v = __floats2half2_rn(acc[i][2], acc[i][3]);
                __half2 h2v = __floats2half2_rn(acc[i][4], acc[i][5]);
                __half2 h3 = __floats2half2_rn(acc[i][6], acc[i][7]);
                uint4 pkt;
                pkt.x = *reinterpret_cast<unsigned int*>(&h0);
                pkt.y = *reinterpret_cast<unsigned int*>(&h1v);
                pkt.z = *reinterpret_cast<unsigned int*>(&h2v);
                pkt.w = *reinterpret_cast<unsigned int*>(&h3);
                *reinterpret_cast<uint4*>(H + (size_t)gr * 128 + tx * 8) = pkt;
            } else {
                __half2 h0 = __floats2half2_rn(acc[i][0], acc[i][1]);
                __half2 h1v = __floats2half2_rn(acc[i][2], acc[i][3]);
                uint2 pkt;
                pkt.x = *reinterpret_cast<unsigned int*>(&h0);
                pkt.y = *reinterpret_cast<unsigned int*>(&h1v);
                *reinterpret_cast<uint2*>(H + (size_t)gr * 80 + tx * 4) = pkt;
                H[(size_t)gr * 80 + 64 + tx] = __float2half_rn(acc[i][4]);
            }
        }
    }

    float av[TN], dv[TN];
    #pragma unroll
    for (int j = 0; j < TN; j++) {
        av[j] = attS[cmap[j]];
        dv[j] = attD[cmap[j]];
    }
    #pragma unroll
    for (int i = 0; i < 4; i++) {
        float ps0 = 0.f, ps1 = 0.f, pd0 = 0.f, pd1 = 0.f;
        #pragma unroll
        for (int j = 0; j < TN; j++) {
            if (cmap[j] < HALF) {
                ps0 = fmaf(acc[i][j], av[j], ps0);
                pd0 = fmaf(acc[i][j], dv[j], pd0);
            } else {
                ps1 = fmaf(acc[i][j], av[j], ps1);
                pd1 = fmaf(acc[i][j], dv[j], pd1);
            }
        }
        #pragma unroll
        for (int o = 1; o < 16; o <<= 1) {
            ps0 += __shfl_xor_sync(FULLM, ps0, o);
            ps1 += __shfl_xor_sync(FULLM, ps1, o);
            pd0 += __shfl_xor_sync(FULLM, pd0, o);
            pd1 += __shfl_xor_sync(FULLM, pd1, o);
        }
        int gr = row0 + ty * 4 + i;
        if (tx == 0 && gr < n) {
            AS[gr] = make_float2(ps0, ps1);
            AD[gr] = make_float2(pd0, pd1);
        }
    }
}

// ---- layer-1 gather: warp per dst node; fp16 rows, fp32 accumulate, unroll 4;
//      output stored fp16 ----
__global__ __launch_bounds__(256)
void gather1_k(const int* __restrict__ rowptr, const int* __restrict__ col,
               const float2* __restrict__ AS, const float2* __restrict__ AD,
               const __half* __restrict__ H, const float* __restrict__ b1,
               __half* __restrict__ OUT, int n)
{
    const int lane = threadIdx.x & 31;
    const int i = (blockIdx.x * blockDim.x + threadIdx.x) >> 5;
    if (i >= n) return;
    const bool hs = lane >= 16;               // head1 for cols >= 64
    const float2 adv = AD[i];
    const float ad = hs ? adv.y : adv.x;

    float4 acc = make_float4(0.f, 0.f, 0.f, 0.f);
    float den = 0.f;
    const int beg = rowptr[i], end = rowptr[i + 1];
    #pragma unroll 4
    for (int e = beg; e < end; e++) {
        const int s = __ldg(col + e);
        const float2 asv = __ldg(AS + s);
        float a = (hs ? asv.y : asv.x) + ad;
        a = a > 0.f ? a : NEG_SLOPE * a;
        const float w = __expf(a);
        den += w;
        const uint2 raw = *reinterpret_cast<const uint2*>(H + (size_t)s * 128 + lane * 4);
        const float2 f01 = __half22float2(*reinterpret_cast<const __half2*>(&raw.x));
        const float2 f23 = __half22float2(*reinterpret_cast<const __half2*>(&raw.y));
        acc.x = fmaf(w, f01.x, acc.x); acc.y = fmaf(w, f01.y, acc.y);
        acc.z = fmaf(w, f23.x, acc.z); acc.w = fmaf(w, f23.y, acc.w);
    }
    // self loop
    {
        const float2 asv = AS[i];
        float a = (hs ? asv.y : asv.x) + ad;
        a = a > 0.f ? a : NEG_SLOPE * a;
        const float w = __expf(a);
        den += w;
        const uint2 raw = *reinterpret_cast<const uint2*>(H + (size_t)i * 128 + lane * 4);
        const float2 f01 = __half22float2(*reinterpret_cast<const __half2*>(&raw.x));
        const float2 f23 = __half22float2(*reinterpret_cast<const __half2*>(&raw.y));
        acc.x = fmaf(w, f01.x, acc.x); acc.y = fmaf(w, f01.y, acc.y);
        acc.z = fmaf(w, f23.x, acc.z); acc.w = fmaf(w, f23.y, acc.w);
    }
    const float inv = 1.0f / den;
    const float4 bv = *reinterpret_cast<const float4*>(b1 + lane * 4);
    __half2 o01 = __floats2half2_rn(acc.x * inv + bv.x, acc.y * inv + bv.y);
    __half2 o23 = __floats2half2_rn(acc.z * inv + bv.z, acc.w * inv + bv.w);
    uint2 pkt;
    pkt.x = *reinterpret_cast<unsigned int*>(&o01);
    pkt.y = *reinterpret_cast<unsigned int*>(&o23);
    *reinterpret_cast<uint2*>(OUT + (size_t)i * 128 + lane * 4) = pkt;
}

// ---- per-column sum / sumsq over agg1 (fp16 in, fp32 accum) ----
__global__ void bnstats_k(const __half* __restrict__ A, float* __restrict__ colsum,
                          float* __restrict__ colsq, int n)
{
    const int c = threadIdx.x;                 // 128 threads
    const int r0 = blockIdx.x * 256;
    const int r1 = min(r0 + 256, n);
    float s = 0.f, q = 0.f;
    for (int r = r0; r < r1; r++) {
        float v = __half2float(A[(size_t)r * 128 + c]);
        s += v; q = fmaf(v, v, q);
    }
    atomicAdd(&colsum[c], s);
    atomicAdd(&colsq[c], q);
}

__global__ void bnfold_k(const float* __restrict__ colsum, const float* __restrict__ colsq,
                         const float* __restrict__ gamma, const float* __restrict__ beta,
                         float* __restrict__ scale, float* __restrict__ shift, int n)
{
    const int t = threadIdx.x;
    float inv_n = 1.0f / (float)n;
    float mean = colsum[t] * inv_n;
    float var  = colsq[t] * inv_n - mean * mean;
    float sc   = gamma[t] * rsqrtf(var + BN_EPS_F);
    scale[t] = sc;
    shift[t] = beta[t] - mean * sc;
}

// ---- layer-2 gather (fp16 rows, unroll 4) + head-mean + bias + log_softmax ----
__global__ __launch_bounds__(256)
void gather2_k(const int* __restrict__ rowptr, const int* __restrict__ col,
               const float2* __restrict__ AS, const float2* __restrict__ AD,
               const __half* __restrict__ H, const float* __restrict__ b2,
               float* __restrict__ out, int n)
{
    const int lane = threadIdx.x & 31;
    const int i = (blockIdx.x * blockDim.x + threadIdx.x) >> 5;
    if (i >= n) return;
    const bool act = lane < 20;               // lane*4 < 80
    const bool hs  = lane >= 10;              // head1 for cols >= 40
    const float2 adv = AD[i];
    const float ad = hs ? adv.y : adv.x;

    float4 acc = make_float4(0.f, 0.f, 0.f, 0.f);
    float den = 0.f;
    const int beg = rowptr[i], end = rowptr[i + 1];
    #pragma unroll 4
    for (int e = beg; e < end; e++) {
        const int s = __ldg(col + e);
        const float2 asv = __ldg(AS + s);
        float a = (hs ? asv.y : asv.x) + ad;
        a = a > 0.f ? a : NEG_SLOPE * a;
        const float w = __expf(a);
        den += w;
        if (act) {
            const uint2 raw = *reinterpret_cast<const uint2*>(H + (size_t)s * 80 + lane * 4);
            const float2 f01 = __half22float2(*reinterpret_cast<const __half2*>(&raw.x));
            const float2 f23 = __half22float2(*reinterpret_cast<const __half2*>(&raw.y));
            acc.x = fmaf(w, f01.x, acc.x); acc.y = fmaf(w, f01.y, acc.y);
            acc.z = fmaf(w, f23.x, acc.z); acc.w = fmaf(w, f23.y, acc.w);
        }
    }
    // self loop
    {
        const float2 asv = AS[i];
        float a = (hs ? asv.y : asv.x) + ad;
        a = a > 0.f ? a : NEG_SLOPE * a;
        const float w = __expf(a);
        den += w;
        if (act) {
            const uint2 raw = *reinterpret_cast<const uint2*>(H + (size_t)i * 80 + lane * 4);
            const float2 f01 = __half22float2(*reinterpret_cast<const __half2*>(&raw.x));
            const float2 f23 = __half22float2(*reinterpret_cast<const __half2*>(&raw.y));
            acc.x = fmaf(w, f01.x, acc.x); acc.y = fmaf(w, f01.y, acc.y);
            acc.z = fmaf(w, f23.x, acc.z); acc.w = fmaf(w, f23.y, acc.w);
        }
    }
    const float inv = 1.0f / den;
    float4 v;
    v.x = acc.x * inv; v.y = acc.y * inv; v.z = acc.z * inv; v.w = acc.w * inv;

    // head mean: lanes 0..9 pair with lanes 10..19
    float4 o;
    o.x = __shfl_sync(FULLM, v.x, lane + 10);
    o.y = __shfl_sync(FULLM, v.y, lane + 10);
    o.z = __shfl_sync(FULLM, v.z, lane + 10);
    o.w = __shfl_sync(FULLM, v.w, lane + 10);

    float4 m = make_float4(-1e30f, -1e30f, -1e30f, -1e30f);
    if (lane < 10) {
        const float4 bv = *reinterpret_cast<const float4*>(b2 + lane * 4);
        m.x = 0.5f * (v.x + o.x) + bv.x;
        m.y = 0.5f * (v.y + o.y) + bv.y;
        m.z = 0.5f * (v.z + o.z) + bv.z;
        m.w = 0.5f * (v.w + o.w) + bv.w;
    }
    float mm = fmaxf(fmaxf(m.x, m.y), fmaxf(m.z, m.w));
    #pragma unroll
    for (int off = 16; off > 0; off >>= 1)
        mm = fmaxf(mm, __shfl_xor_sync(FULLM, mm, off));
    float ssum = 0.f;
    if (lane < 10)
        ssum = __expf(m.x - mm) + __expf(m.y - mm) + __expf(m.z - mm) + __expf(m.w - mm);
    #pragma unroll
    for (int off = 16; off > 0; off >>= 1)
        ssum += __shfl_xor_sync(FULLM, ssum, off);
    const float lse = mm + __logf(ssum);

    if (lane < 10) {
        float4 r;
        r.x = m.x - lse; r.y = m.y - lse; r.z = m.z - lse; r.w = m.w - lse;
        *reinterpret_cast<float4*>(out + (size_t)i * 40 + lane * 4) = r;
    }
}

// ------------------------------- launcher -------------------------------
extern "C" void kernel_launch(void* const* d_in, const int* in_sizes, int n_in,
                              void* d_out, int out_size)
{
    const float* x      = (const float*)d_in[0];
    const int*   ei     = (const int*)  d_in[1];
    const float* W1     = (const float*)d_in[2];
    const float* att_s1 = (const float*)d_in[3];
    const float* att_d1 = (const float*)d_in[4];
    const float* b1     = (const float*)d_in[5];
    const float* gamma  = (const float*)d_in[6];
    const float* beta   = (const float*)d_in[7];
    const float* W2     = (const float*)d_in[8];
    const float* att_s2 = (const float*)d_in[9];
    const float* att_d2 = (const float*)d_in[10];
    const float* b2     = (const float*)d_in[11];
    float* out = (float*)d_out;

    const int n = in_sizes[0] / 128;
    const int E = in_sizes[1] / 2;
    const int* src = ei;
    const int* dst = ei + E;

    float *colsum, *colsq, *scale, *shift;
    __half *h1, *h2, *agg1;
    float2 *as1, *ad1, *as2, *ad2;
    int *deg, *incl, *rowptr, *cursor, *colarr, *bsum;
    cudaGetSymbolAddress((void**)&h1,     g_h1);
    cudaGetSymbolAddress((void**)&agg1,   g_agg1);
    cudaGetSymbolAddress((void**)&h2,     g_h2);
    cudaGetSymbolAddress((void**)&as1,    g_as1);
    cudaGetSymbolAddress((void**)&ad1,    g_ad1);
    cudaGetSymbolAddress((void**)&as2,    g_as2);
    cudaGetSymbolAddress((void**)&ad2,    g_ad2);
    cudaGetSymbolAddress((void**)&deg,    g_deg);
    cudaGetSymbolAddress((void**)&incl,   g_incl);
    cudaGetSymbolAddress((void**)&rowptr, g_rowptr);
    cudaGetSymbolAddress((void**)&cursor, g_cursor);
    cudaGetSymbolAddress((void**)&colarr, g_col);
    cudaGetSymbolAddress((void**)&bsum,   g_bsum);
    cudaGetSymbolAddress((void**)&colsum, g_colsum);
    cudaGetSymbolAddress((void**)&colsq,  g_colsq);
    cudaGetSymbolAddress((void**)&scale,  g_scale);
    cudaGetSymbolAddress((void**)&shift,  g_shift);

    // smem: W fp16 + X fp16 + out fp32(padded)
    const size_t smem1 = (size_t)128 * 128 * 2 + 64 * 128 * 2 + 64 * 136 * 4; // 83968
    const size_t smem2 = (size_t)128 * 80  * 2 + 64 * 128 * 2 + 64 * 88  * 4; // 59392
    cudaFuncSetAttribute((const void*)gemm_k<128, float>,
                         cudaFuncAttributeMaxDynamicSharedMemorySize, (int)smem1);
    cudaFuncSetAttribute((const void*)gemm_k<80, __half>,
                         cudaFuncAttributeMaxDynamicSharedMemorySize, (int)smem2);

    const int gb = (n + 63) / 64;         // gemm blocks
    const int wb = (n * 32 + 255) / 256;  // warp-per-node blocks
    const int nb = (n + 1023) / 1024;     // scan blocks

    // ---- CSR build (shared by both layers) ----
    zero_init_k<<<(n + 255) / 256, 256>>>(deg, colsum, colsq, n);    // launch 1
    hist_k<<<(E + 255) / 256, 256>>>(dst, deg, E);                   // 2
    scan1_k<<<nb, 1024>>>(deg, incl, bsum, n);                       // 3
    scan3_k<<<(n + 255) / 256, 256>>>(incl, bsum, deg, rowptr, cursor, n, nb); // 4
    fill_k<<<(E + 255) / 256, 256>>>(src, dst, cursor, colarr, E);   // 5

    // ---- layer 1 ----
    gemm_k<128, float><<<gb, 256, smem1>>>(x, W1, h1, n, nullptr, nullptr, // 6 <- ncu
                                           att_s1, att_d1, as1, ad1);
    gather1_k<<<wb, 256>>>(rowptr, colarr, as1, ad1, h1, b1, agg1, n);

    // ---- batchnorm stats + fold ----
    bnstats_k<<<(n + 255) / 256, 128>>>(agg1, colsum, colsq, n);
    bnfold_k<<<1, 128>>>(colsum, colsq, gamma, beta, scale, shift, n);

    // ---- layer 2 (BN folded into GEMM A-load, fp16 input) ----
    gemm_k<80, __half><<<gb, 256, smem2>>>(agg1, W2, h2, n, scale, shift,
                                           att_s2, att_d2, as2, ad2);
    gather2_k<<<wb, 256>>>(rowptr, colarr, as2, ad2, h2, b2, out, n);
}